// round 1
// baseline (speedup 1.0000x reference)
#include <cuda_runtime.h>
#include <math.h>

#define B_   32
#define T_   2000
#define H_   256
#define S_   63
#define TM1  1999            // T-1
#define M1   63968           // B*(T-1)
#define M1P  64000           // padded row count (128*500)
#define K1   512             // 2*H
#define N1   256             // H

// Scratch (device globals: allocation-guard safe)
__device__ float g_h[M1P * H_];       // hidden activations, padded rows are garbage
__device__ float g_trans[M1P * S_];   // transition scores, indexed (b*1999+t)*63

// ---------------------------------------------------------------------------
// GEMM1: h = relu(pairs @ W1 + b1)
//   pairs[m, k] = k<256 ? emb[b, t+1, k] : emb[b, t, k-256],  m = b*1999+t
//   M=64000 (padded, rows>=63968 clamped), N=256, K=512
//   128x128 tile, BK=8, 256 threads, 8x8 per-thread microtile
// ---------------------------------------------------------------------------
__global__ __launch_bounds__(256) void gemm1_kernel(
    const float* __restrict__ emb, const float* __restrict__ W1,
    const float* __restrict__ b1)
{
    __shared__ float As[8][128];
    __shared__ float Bs[8][128];

    const int tid   = threadIdx.x;
    const int mBase = blockIdx.y * 128;
    const int nBase = blockIdx.x * 128;

    // A-tile load mapping: each thread loads one float4 (4 consecutive k)
    const int aRow = tid >> 1;             // 0..127
    const int aK4  = (tid & 1) * 4;        // 0 or 4
    int m  = mBase + aRow;
    int mm = m < M1 ? m : (M1 - 1);
    int b  = mm / TM1;
    int t  = mm - b * TM1;
    const float* rowT   = emb + ((long)b * T_ + t) * H_;  // k>=256: rowT[k-256]
    const float* rowTp1 = rowT + H_;                      // k<256 : rowTp1[k]

    // B-tile load mapping: each thread loads one float4 of W1
    const int bK  = tid >> 5;              // 0..7
    const int bN4 = (tid & 31) * 4;        // 0..124

    const int tx = tid & 15;               // n-thread
    const int ty = tid >> 4;               // m-thread

    float acc[8][8];
    #pragma unroll
    for (int i = 0; i < 8; i++)
        #pragma unroll
        for (int j = 0; j < 8; j++) acc[i][j] = 0.f;

    for (int kb = 0; kb < K1; kb += 8) {
        int kg = kb + aK4;
        const float* src = (kg < H_) ? (rowTp1 + kg) : (rowT + (kg - H_));
        float4 av = *reinterpret_cast<const float4*>(src);
        As[aK4 + 0][aRow] = av.x;
        As[aK4 + 1][aRow] = av.y;
        As[aK4 + 2][aRow] = av.z;
        As[aK4 + 3][aRow] = av.w;

        float4 bv = *reinterpret_cast<const float4*>(W1 + (long)(kb + bK) * N1 + nBase + bN4);
        *reinterpret_cast<float4*>(&Bs[bK][bN4]) = bv;

        __syncthreads();

        #pragma unroll
        for (int k = 0; k < 8; k++) {
            float4 a0 = *reinterpret_cast<const float4*>(&As[k][ty * 8]);
            float4 a1 = *reinterpret_cast<const float4*>(&As[k][ty * 8 + 4]);
            float4 b0 = *reinterpret_cast<const float4*>(&Bs[k][tx * 8]);
            float4 b1v = *reinterpret_cast<const float4*>(&Bs[k][tx * 8 + 4]);
            float ra[8] = {a0.x, a0.y, a0.z, a0.w, a1.x, a1.y, a1.z, a1.w};
            float rb[8] = {b0.x, b0.y, b0.z, b0.w, b1v.x, b1v.y, b1v.z, b1v.w};
            #pragma unroll
            for (int i = 0; i < 8; i++)
                #pragma unroll
                for (int j = 0; j < 8; j++)
                    acc[i][j] = fmaf(ra[i], rb[j], acc[i][j]);
        }
        __syncthreads();
    }

    // Epilogue: +b1, relu, store to g_h (padded rows written harmlessly)
    float bias[8];
    #pragma unroll
    for (int j = 0; j < 8; j++) bias[j] = __ldg(&b1[nBase + tx * 8 + j]);

    #pragma unroll
    for (int i = 0; i < 8; i++) {
        int mo = mBase + ty * 8 + i;
        float* dst = &g_h[(long)mo * H_ + nBase + tx * 8];
        float4 o0, o1;
        o0.x = fmaxf(acc[i][0] + bias[0], 0.f);
        o0.y = fmaxf(acc[i][1] + bias[1], 0.f);
        o0.z = fmaxf(acc[i][2] + bias[2], 0.f);
        o0.w = fmaxf(acc[i][3] + bias[3], 0.f);
        o1.x = fmaxf(acc[i][4] + bias[4], 0.f);
        o1.y = fmaxf(acc[i][5] + bias[5], 0.f);
        o1.z = fmaxf(acc[i][6] + bias[6], 0.f);
        o1.w = fmaxf(acc[i][7] + bias[7], 0.f);
        *reinterpret_cast<float4*>(dst)     = o0;
        *reinterpret_cast<float4*>(dst + 4) = o1;
    }
}

// ---------------------------------------------------------------------------
// GEMM2: trans = h @ W2 + b2
//   M=64000 (padded), N=63 (tile 64, guarded), K=256
//   128x64 tile, BK=8, 256 threads, 8x4 per-thread microtile
// ---------------------------------------------------------------------------
__global__ __launch_bounds__(256) void gemm2_kernel(
    const float* __restrict__ W2, const float* __restrict__ b2)
{
    __shared__ float As[8][128];
    __shared__ float Bs[8][64];

    const int tid   = threadIdx.x;
    const int mBase = blockIdx.y * 128;

    const int aRow = tid >> 1;
    const int aK4  = (tid & 1) * 4;
    const int am   = mBase + aRow;

    // B-tile: 512 floats, 2 scalars per thread
    const int bIdx = tid * 2;
    const int bK   = bIdx >> 6;            // 0..7
    const int bN   = bIdx & 63;            // 0..62 (even)

    const int tx = tid & 15;               // n-thread (4 cols)
    const int ty = tid >> 4;               // m-thread (8 rows)

    float acc[8][4];
    #pragma unroll
    for (int i = 0; i < 8; i++)
        #pragma unroll
        for (int j = 0; j < 4; j++) acc[i][j] = 0.f;

    for (int kb = 0; kb < H_; kb += 8) {
        float4 av = *reinterpret_cast<const float4*>(&g_h[(long)am * H_ + kb + aK4]);
        As[aK4 + 0][aRow] = av.x;
        As[aK4 + 1][aRow] = av.y;
        As[aK4 + 2][aRow] = av.z;
        As[aK4 + 3][aRow] = av.w;

        #pragma unroll
        for (int q = 0; q < 2; q++) {
            int n = bN + q;
            Bs[bK][n] = (n < S_) ? __ldg(&W2[(long)(kb + bK) * S_ + n]) : 0.f;
        }
        __syncthreads();

        #pragma unroll
        for (int k = 0; k < 8; k++) {
            float4 a0 = *reinterpret_cast<const float4*>(&As[k][ty * 8]);
            float4 a1 = *reinterpret_cast<const float4*>(&As[k][ty * 8 + 4]);
            float4 bvv = *reinterpret_cast<const float4*>(&Bs[k][tx * 4]);
            float ra[8] = {a0.x, a0.y, a0.z, a0.w, a1.x, a1.y, a1.z, a1.w};
            float rb[4] = {bvv.x, bvv.y, bvv.z, bvv.w};
            #pragma unroll
            for (int i = 0; i < 8; i++)
                #pragma unroll
                for (int j = 0; j < 4; j++)
                    acc[i][j] = fmaf(ra[i], rb[j], acc[i][j]);
        }
        __syncthreads();
    }

    #pragma unroll
    for (int j = 0; j < 4; j++) {
        int n = tx * 4 + j;
        if (n < S_) {
            float bias = __ldg(&b2[n]);
            #pragma unroll
            for (int i = 0; i < 8; i++) {
                int mo = mBase + ty * 8 + i;
                g_trans[(long)mo * S_ + n] = acc[i][j] + bias;
            }
        }
    }
}

// ---------------------------------------------------------------------------
// Align: softmax over collapsed forward-backward scores. One warp per (b,t).
// ---------------------------------------------------------------------------
__global__ __launch_bounds__(256) void align_kernel(
    const float* __restrict__ logits, const int* __restrict__ kw,
    float* __restrict__ out)
{
    const int warp = threadIdx.x >> 5;
    const int lane = threadIdx.x & 31;
    const int r = blockIdx.x * 8 + warp;        // (b,t) flat index, grid sized exactly
    const int b = r / T_;
    const int t = r - b * T_;

    const float* Lb  = logits  + (long)b * T_ * S_;
    const float* Trb = g_trans + (long)b * TM1 * S_;

    const int s0 = lane;
    const int s1 = lane + 32;
    const bool has1 = (s1 < S_);

    float v0, v1;
    if (t == 0) {
        // LSE over logits[b,0,:]
        float a0 = Lb[s0];
        float a1 = has1 ? Lb[s1] : -INFINITY;
        float mx = fmaxf(a0, a1);
        #pragma unroll
        for (int o = 16; o > 0; o >>= 1) mx = fmaxf(mx, __shfl_xor_sync(0xffffffff, mx, o));
        float se = __expf(a0 - mx) + (has1 ? __expf(a1 - mx) : 0.f);
        #pragma unroll
        for (int o = 16; o > 0; o >>= 1) se += __shfl_xor_sync(0xffffffff, se, o);
        float lse = mx + __logf(se);
        int k0 = __ldg(&kw[b * 32]);
        float logp0 = Lb[k0] - lse;
        v0 = ((s0 == 0) ? logp0 : 0.f) + Lb[S_ + s0] + Trb[s0];
        v1 = has1 ? (Lb[S_ + s1] + Trb[s1]) : -INFINITY;
    } else if (t == T_ - 1) {
        v0 = Lb[(long)t * S_ + s0] + Trb[(long)(t - 1) * S_ + s0];
        v1 = has1 ? (Lb[(long)t * S_ + s1] + Trb[(long)(t - 1) * S_ + s1]) : -INFINITY;
    } else {
        v0 = Lb[(long)t * S_ + s0] + Lb[(long)(t + 1) * S_ + s0]
           + Trb[(long)(t - 1) * S_ + s0] + Trb[(long)t * S_ + s0];
        v1 = has1 ? (Lb[(long)t * S_ + s1] + Lb[(long)(t + 1) * S_ + s1]
                   + Trb[(long)(t - 1) * S_ + s1] + Trb[(long)t * S_ + s1])
                  : -INFINITY;
    }

    // softmax over 63 states within the warp
    float mx = fmaxf(v0, v1);
    #pragma unroll
    for (int o = 16; o > 0; o >>= 1) mx = fmaxf(mx, __shfl_xor_sync(0xffffffff, mx, o));
    float e0 = expf(v0 - mx);
    float e1 = has1 ? expf(v1 - mx) : 0.f;
    float sum = e0 + e1;
    #pragma unroll
    for (int o = 16; o > 0; o >>= 1) sum += __shfl_xor_sync(0xffffffff, sum, o);
    float inv = 1.f / sum;

    float* ob = out + (long)r * S_;
    ob[s0] = e0 * inv;
    if (has1) ob[s1] = e1 * inv;
}

// ---------------------------------------------------------------------------
extern "C" void kernel_launch(void* const* d_in, const int* in_sizes, int n_in,
                              void* d_out, int out_size) {
    const float* logits = (const float*)d_in[0];   // (B,T,S)
    const float* emb    = (const float*)d_in[1];   // (B,T,H)
    const int*   kw     = (const int*)  d_in[2];   // (B,32)
    const float* W1     = (const float*)d_in[3];   // (2H,H)
    const float* b1     = (const float*)d_in[4];   // (H,)
    const float* W2     = (const float*)d_in[5];   // (H,S)
    const float* b2     = (const float*)d_in[6];   // (S,)
    float*       out    = (float*)d_out;           // (B,T,S)

    gemm1_kernel<<<dim3(2, 500), 256>>>(emb, W1, b1);
    gemm2_kernel<<<dim3(1, 500), 256>>>(W2, b2);
    align_kernel<<<(B_ * T_) / 8, 256>>>(logits, kw, out);
}

// round 3
// speedup vs baseline: 2.2465x; 2.2465x over previous
#include <cuda_runtime.h>
#include <math.h>
#include <cstdint>

#define B_   32
#define T_   2000
#define H_   256
#define S_   63
#define TM1  1999            // T-1
#define M1   63968           // B*(T-1)
#define M1P  64000           // padded row count (128*500)
#define K1   512             // 2*H
#define N1   256             // H

// Scratch (device globals: allocation-guard safe)
__device__ __align__(16) float    g_hT[N1 * M1P];        // hidden^T [n][m]
__device__ __align__(16) float    g_trans[M1P * S_];     // transition scores
__device__ __align__(16) uint32_t g_w1pack[N1 * K1];     // W1^T tf32 bits, fragment-packed

__device__ __forceinline__ uint32_t f2tf32(float f) {
    uint32_t r;
    asm("cvt.rna.tf32.f32 %0, %1;" : "=r"(r) : "f"(f));
    return r;
}

__device__ __forceinline__ void mma_tf32(float* c, uint32_t a0, uint32_t a1,
                                         uint32_t a2, uint32_t a3,
                                         uint32_t b0, uint32_t b1) {
    asm volatile(
        "mma.sync.aligned.m16n8k8.row.col.f32.tf32.tf32.f32 "
        "{%0,%1,%2,%3}, {%4,%5,%6,%7}, {%8,%9}, {%0,%1,%2,%3};"
        : "+f"(c[0]), "+f"(c[1]), "+f"(c[2]), "+f"(c[3])
        : "r"(a0), "r"(a1), "r"(a2), "r"(a3), "r"(b0), "r"(b1));
}

// ===========================================================================
// Prep: pack W1^T into per-lane tf32 fragment order.
// Fragment addressing: idx = ((((nt*4+q)*64 + ks)*2 + s)*32 + lane)*4 + {0..3}
//   a0 = W1T[n0][k0], a1 = W1T[n0+8][k0], a2 = W1T[n0][k0+4], a3 = W1T[n0+8][k0+4]
//   n0 = nt*128 + q*32 + s*16 + lane/4,  k0 = ks*8 + lane%4
//   W1T[n][k] = W1[k*256 + n]
// ===========================================================================
__global__ __launch_bounds__(256) void prep_w1(const float* __restrict__ W1) {
    int idx  = blockIdx.x * 256 + threadIdx.x;   // 0..32767
    int lane = idx & 31;
    int s    = (idx >> 5) & 1;
    int ks   = (idx >> 6) & 63;
    int q    = (idx >> 12) & 3;
    int nt   = idx >> 14;

    int n0 = nt * 128 + q * 32 + s * 16 + (lane >> 2);
    int k0 = ks * 8 + (lane & 3);

    uint4 o;
    o.x = f2tf32(W1[(long)k0 * N1 + n0]);
    o.y = f2tf32(W1[(long)k0 * N1 + n0 + 8]);
    o.z = f2tf32(W1[(long)(k0 + 4) * N1 + n0]);
    o.w = f2tf32(W1[(long)(k0 + 4) * N1 + n0 + 8]);
    *reinterpret_cast<uint4*>(&g_w1pack[(long)idx * 4]) = o;
}

// ===========================================================================
// GEMM1 (tensor, tf32 mma.sync): hT = relu(W1^T @ pairs^T + b1)
//   D tile per CTA: 128(N) x 128(M); warp tile 32(N) x 64(M); K=512, ktile=32.
//   grid = (500 m-tiles, 2 n-tiles)
// ===========================================================================
#define BSTRIDE 36
__global__ __launch_bounds__(256, 2) void gemm1_tc(
    const float* __restrict__ emb, const float* __restrict__ b1)
{
    __shared__ uint32_t sB[128 * BSTRIDE];   // pairs^T tile [m 128][k 32], tf32 bits

    const int tid  = threadIdx.x;
    const int warp = tid >> 5;
    const int lane = tid & 31;
    const int wq   = warp & 3;     // n 32-block
    const int wm   = warp >> 2;    // m 64-block
    const int mBase = blockIdx.x * 128;
    const int nt    = blockIdx.y;

    // B-stage mapping: thread handles row r, one 16-col half
    const int r  = tid >> 1;
    const int ch = (tid & 1) * 16;
    int m = mBase + r;
    if (m >= M1) m = M1 - 1;
    const int b = m / TM1;
    const int t = m - b * TM1;
    const float* rowT  = emb + ((long)b * T_ + t) * H_;   // pairs k>=256
    const float* rowT1 = rowT + H_;                       // pairs k<256

    float acc[2][8][4];
    #pragma unroll
    for (int s = 0; s < 2; s++)
        #pragma unroll
        for (int j = 0; j < 8; j++)
            #pragma unroll
            for (int d = 0; d < 4; d++) acc[s][j][d] = 0.f;

    const uint4* wpack = reinterpret_cast<const uint4*>(g_w1pack);

    for (int kt = 0; kt < 16; kt++) {
        if (kt) __syncthreads();

        // stage B: 128 x 32 fp32 -> tf32 bits, row stride 36
        const int kg = kt * 32;
        const float* src = (kg < H_) ? (rowT1 + kg) : (rowT + (kg - H_));
        #pragma unroll
        for (int u = 0; u < 4; u++) {
            float4 v = *reinterpret_cast<const float4*>(src + ch + u * 4);
            uint32_t* d = &sB[r * BSTRIDE + ch + u * 4];
            d[0] = f2tf32(v.x);
            d[1] = f2tf32(v.y);
            d[2] = f2tf32(v.z);
            d[3] = f2tf32(v.w);
        }
        __syncthreads();

        #pragma unroll
        for (int ks = 0; ks < 4; ks++) {
            // A fragments: one LDG.128 each (prepacked), s=0 and s=1
            long aIdx = (((long)(nt * 4 + wq) * 64 + kt * 4 + ks) * 2) * 32 + lane;
            uint4 A0 = wpack[aIdx];
            uint4 A1 = wpack[aIdx + 32];

            #pragma unroll
            for (int j = 0; j < 8; j++) {
                int mloc = wm * 64 + j * 8 + (lane >> 2);
                uint32_t b0 = sB[mloc * BSTRIDE + ks * 8 + (lane & 3)];
                uint32_t b1v = sB[mloc * BSTRIDE + ks * 8 + (lane & 3) + 4];
                mma_tf32(acc[0][j], A0.x, A0.y, A0.z, A0.w, b0, b1v);
                mma_tf32(acc[1][j], A1.x, A1.y, A1.z, A1.w, b0, b1v);
            }
        }
    }

    // Epilogue: +b1, relu, store hT[n][m]  (d0,d1 -> (n, m..m+1); d2,d3 -> n+8)
    #pragma unroll
    for (int s = 0; s < 2; s++) {
        int n_g = nt * 128 + wq * 32 + s * 16 + (lane >> 2);
        float bn0 = __ldg(&b1[n_g]);
        float bn8 = __ldg(&b1[n_g + 8]);
        #pragma unroll
        for (int j = 0; j < 8; j++) {
            int m_g = mBase + wm * 64 + j * 8 + (lane & 3) * 2;
            float2 o0, o8;
            o0.x = fmaxf(acc[s][j][0] + bn0, 0.f);
            o0.y = fmaxf(acc[s][j][1] + bn0, 0.f);
            o8.x = fmaxf(acc[s][j][2] + bn8, 0.f);
            o8.y = fmaxf(acc[s][j][3] + bn8, 0.f);
            *reinterpret_cast<float2*>(&g_hT[(long)n_g * M1P + m_g])       = o0;
            *reinterpret_cast<float2*>(&g_hT[(long)(n_g + 8) * M1P + m_g]) = o8;
        }
    }
}

// ===========================================================================
// GEMM2 (SIMT): trans = h @ W2 + b2, reading hT [k][m].  M=64000, N=63, K=256.
// ===========================================================================
__global__ __launch_bounds__(256) void gemm2_kernel(
    const float* __restrict__ W2, const float* __restrict__ b2)
{
    __shared__ float As[8][128];
    __shared__ float Bs[8][64];

    const int tid   = threadIdx.x;
    const int mBase = blockIdx.y * 128;

    // A-tile load: k = tid/32 (0..7), m4 = (tid%32)*4 — coalesced from hT
    const int akk = tid >> 5;
    const int am4 = (tid & 31) * 4;

    const int bIdx = tid * 2;
    const int bK   = bIdx >> 6;
    const int bN   = bIdx & 63;

    const int tx = tid & 15;
    const int ty = tid >> 4;

    float acc[8][4];
    #pragma unroll
    for (int i = 0; i < 8; i++)
        #pragma unroll
        for (int j = 0; j < 4; j++) acc[i][j] = 0.f;

    for (int kb = 0; kb < H_; kb += 8) {
        *reinterpret_cast<float4*>(&As[akk][am4]) =
            *reinterpret_cast<const float4*>(&g_hT[(long)(kb + akk) * M1P + mBase + am4]);

        #pragma unroll
        for (int q = 0; q < 2; q++) {
            int n = bN + q;
            Bs[bK][n] = (n < S_) ? __ldg(&W2[(long)(kb + bK) * S_ + n]) : 0.f;
        }
        __syncthreads();

        #pragma unroll
        for (int k = 0; k < 8; k++) {
            float4 a0 = *reinterpret_cast<const float4*>(&As[k][ty * 8]);
            float4 a1 = *reinterpret_cast<const float4*>(&As[k][ty * 8 + 4]);
            float4 bvv = *reinterpret_cast<const float4*>(&Bs[k][tx * 4]);
            float ra[8] = {a0.x, a0.y, a0.z, a0.w, a1.x, a1.y, a1.z, a1.w};
            float rb[4] = {bvv.x, bvv.y, bvv.z, bvv.w};
            #pragma unroll
            for (int i = 0; i < 8; i++)
                #pragma unroll
                for (int j = 0; j < 4; j++)
                    acc[i][j] = fmaf(ra[i], rb[j], acc[i][j]);
        }
        __syncthreads();
    }

    #pragma unroll
    for (int j = 0; j < 4; j++) {
        int n = tx * 4 + j;
        if (n < S_) {
            float bias = __ldg(&b2[n]);
            #pragma unroll
            for (int i = 0; i < 8; i++) {
                int mo = mBase + ty * 8 + i;
                g_trans[(long)mo * S_ + n] = acc[i][j] + bias;
            }
        }
    }
}

// ===========================================================================
// Align: softmax over collapsed forward-backward scores. One warp per (b,t).
// ===========================================================================
__global__ __launch_bounds__(256) void align_kernel(
    const float* __restrict__ logits, const int* __restrict__ kw,
    float* __restrict__ out)
{
    const int warp = threadIdx.x >> 5;
    const int lane = threadIdx.x & 31;
    const int r = blockIdx.x * 8 + warp;
    const int b = r / T_;
    const int t = r - b * T_;

    const float* Lb  = logits  + (long)b * T_ * S_;
    const float* Trb = g_trans + (long)b * TM1 * S_;

    const int s0 = lane;
    const int s1 = lane + 32;
    const bool has1 = (s1 < S_);

    float v0, v1;
    if (t == 0) {
        float a0 = Lb[s0];
        float a1 = has1 ? Lb[s1] : -INFINITY;
        float mx = fmaxf(a0, a1);
        #pragma unroll
        for (int o = 16; o > 0; o >>= 1) mx = fmaxf(mx, __shfl_xor_sync(0xffffffff, mx, o));
        float se = __expf(a0 - mx) + (has1 ? __expf(a1 - mx) : 0.f);
        #pragma unroll
        for (int o = 16; o > 0; o >>= 1) se += __shfl_xor_sync(0xffffffff, se, o);
        float lse = mx + __logf(se);
        int k0 = __ldg(&kw[b * 32]);
        float logp0 = Lb[k0] - lse;
        v0 = ((s0 == 0) ? logp0 : 0.f) + Lb[S_ + s0] + Trb[s0];
        v1 = has1 ? (Lb[S_ + s1] + Trb[s1]) : -INFINITY;
    } else if (t == T_ - 1) {
        v0 = Lb[(long)t * S_ + s0] + Trb[(long)(t - 1) * S_ + s0];
        v1 = has1 ? (Lb[(long)t * S_ + s1] + Trb[(long)(t - 1) * S_ + s1]) : -INFINITY;
    } else {
        v0 = Lb[(long)t * S_ + s0] + Lb[(long)(t + 1) * S_ + s0]
           + Trb[(long)(t - 1) * S_ + s0] + Trb[(long)t * S_ + s0];
        v1 = has1 ? (Lb[(long)t * S_ + s1] + Lb[(long)(t + 1) * S_ + s1]
                   + Trb[(long)(t - 1) * S_ + s1] + Trb[(long)t * S_ + s1])
                  : -INFINITY;
    }

    float mx = fmaxf(v0, v1);
    #pragma unroll
    for (int o = 16; o > 0; o >>= 1) mx = fmaxf(mx, __shfl_xor_sync(0xffffffff, mx, o));
    float e0 = expf(v0 - mx);
    float e1 = has1 ? expf(v1 - mx) : 0.f;
    float sum = e0 + e1;
    #pragma unroll
    for (int o = 16; o > 0; o >>= 1) sum += __shfl_xor_sync(0xffffffff, sum, o);
    float inv = 1.f / sum;

    float* ob = out + (long)r * S_;
    ob[s0] = e0 * inv;
    if (has1) ob[s1] = e1 * inv;
}

// ===========================================================================
extern "C" void kernel_launch(void* const* d_in, const int* in_sizes, int n_in,
                              void* d_out, int out_size) {
    const float* logits = (const float*)d_in[0];   // (B,T,S)
    const float* emb    = (const float*)d_in[1];   // (B,T,H)
    const int*   kw     = (const int*)  d_in[2];   // (B,32)
    const float* W1     = (const float*)d_in[3];   // (2H,H)
    const float* b1     = (const float*)d_in[4];   // (H,)
    const float* W2     = (const float*)d_in[5];   // (H,S)
    const float* b2     = (const float*)d_in[6];   // (S,)
    float*       out    = (float*)d_out;           // (B,T,S)

    prep_w1<<<128, 256>>>(W1);
    gemm1_tc<<<dim3(500, 2), 256>>>(emb, b1);
    gemm2_kernel<<<dim3(1, 500), 256>>>(W2, b2);
    align_kernel<<<(B_ * T_) / 8, 256>>>(logits, kw, out);
}

// round 4
// speedup vs baseline: 2.7795x; 1.2373x over previous
#include <cuda_runtime.h>
#include <math.h>
#include <cstdint>

#define B_   32
#define T_   2000
#define H_   256
#define S_   63
#define TM1  1999            // T-1
#define M1   63968           // B*(T-1)
#define M1P  64000           // padded row count (128*500)
#define K1   512             // 2*H
#define N1   256             // H

// Scratch (device globals: allocation-guard safe)
__device__ __align__(16) uint32_t g_hT[N1 * M1P];        // hidden^T [n][m], tf32 BITS
__device__ __align__(16) float    g_trans[M1P * S_];     // transition scores
__device__ __align__(16) uint32_t g_w1pack[N1 * K1];     // W1^T tf32, A-fragment-packed
__device__ __align__(16) uint32_t g_w2pack[32 * 8 * 32 * 2]; // W2 tf32, B-fragment-packed

__device__ __forceinline__ uint32_t f2tf32(float f) {
    uint32_t r;
    asm("cvt.rna.tf32.f32 %0, %1;" : "=r"(r) : "f"(f));
    return r;
}

__device__ __forceinline__ void mma_tf32(float* c, uint32_t a0, uint32_t a1,
                                         uint32_t a2, uint32_t a3,
                                         uint32_t b0, uint32_t b1) {
    asm volatile(
        "mma.sync.aligned.m16n8k8.row.col.f32.tf32.tf32.f32 "
        "{%0,%1,%2,%3}, {%4,%5,%6,%7}, {%8,%9}, {%0,%1,%2,%3};"
        : "+f"(c[0]), "+f"(c[1]), "+f"(c[2]), "+f"(c[3])
        : "r"(a0), "r"(a1), "r"(a2), "r"(a3), "r"(b0), "r"(b1));
}

// ===========================================================================
// Prep W1: pack W1^T into per-lane tf32 A-fragment order (validated R3).
// ===========================================================================
__global__ __launch_bounds__(256) void prep_w1(const float* __restrict__ W1) {
    int idx  = blockIdx.x * 256 + threadIdx.x;   // 0..32767
    int lane = idx & 31;
    int s    = (idx >> 5) & 1;
    int ks   = (idx >> 6) & 63;
    int q    = (idx >> 12) & 3;
    int nt   = idx >> 14;

    int n0 = nt * 128 + q * 32 + s * 16 + (lane >> 2);
    int k0 = ks * 8 + (lane & 3);

    uint4 o;
    o.x = f2tf32(W1[(long)k0 * N1 + n0]);
    o.y = f2tf32(W1[(long)k0 * N1 + n0 + 8]);
    o.z = f2tf32(W1[(long)(k0 + 4) * N1 + n0]);
    o.w = f2tf32(W1[(long)(k0 + 4) * N1 + n0 + 8]);
    *reinterpret_cast<uint4*>(&g_w1pack[(long)idx * 4]) = o;
}

// ===========================================================================
// Prep W2: pack W2 [K=256][S=63] into per-lane tf32 B-fragment order.
//   b0 = W2[kt*8 + lane%4][nb*8 + lane/4], b1 = same with k+4.  n=63 padded 0.
// ===========================================================================
__global__ __launch_bounds__(256) void prep_w2(const float* __restrict__ W2) {
    int idx  = blockIdx.x * 256 + threadIdx.x;   // 0..8191
    int lane = idx & 31;
    int nb   = (idx >> 5) & 7;
    int kt   = idx >> 8;
    int k = kt * 8 + (lane & 3);
    int n = nb * 8 + (lane >> 2);
    float w0 = (n < S_) ? W2[(long)k * S_ + n] : 0.f;
    float w1 = (n < S_) ? W2[(long)(k + 4) * S_ + n] : 0.f;
    uint2 o;
    o.x = f2tf32(w0);
    o.y = f2tf32(w1);
    *reinterpret_cast<uint2*>(&g_w2pack[(long)idx * 2]) = o;
}

// ===========================================================================
// GEMM1 (tf32 mma.sync, double-buffered): hT = relu(W1^T @ pairs^T + b1)
//   CTA tile 128(N) x 128(M); warp tile 32(N) x 64(M); K=512, ktile=32.
//   Output stored as tf32 bits (consumed directly by gemm2).
// ===========================================================================
#define BST 36
__global__ __launch_bounds__(256, 2) void gemm1_tc(
    const float* __restrict__ emb, const float* __restrict__ b1)
{
    __shared__ uint32_t sB[2][128 * BST];   // pairs^T tile [m 128][k 32], tf32 bits

    const int tid  = threadIdx.x;
    const int warp = tid >> 5;
    const int lane = tid & 31;
    const int wq   = warp & 3;     // n 32-block
    const int wm   = warp >> 2;    // m 64-block
    const int mBase = blockIdx.x * 128;
    const int nt    = blockIdx.y;

    // B-stage mapping: thread handles row r, one 16-col half
    const int r  = tid >> 1;
    const int ch = (tid & 1) * 16;
    int m = mBase + r;
    if (m >= M1) m = M1 - 1;
    const int b = m / TM1;
    const int t = m - b * TM1;
    const float* rowT  = emb + ((long)b * T_ + t) * H_;   // pairs k>=256
    const float* rowT1 = rowT + H_;                       // pairs k<256

    float acc[2][8][4];
    #pragma unroll
    for (int s = 0; s < 2; s++)
        #pragma unroll
        for (int j = 0; j < 8; j++)
            #pragma unroll
            for (int d = 0; d < 4; d++) acc[s][j][d] = 0.f;

    const uint4* wpack = reinterpret_cast<const uint4*>(g_w1pack);

    // prologue: stage kt=0
    {
        const float* src = rowT1;   // kt=0 -> kg=0 < H_
        #pragma unroll
        for (int u = 0; u < 4; u++) {
            float4 v = *reinterpret_cast<const float4*>(src + ch + u * 4);
            uint4 o;
            o.x = f2tf32(v.x); o.y = f2tf32(v.y); o.z = f2tf32(v.z); o.w = f2tf32(v.w);
            *reinterpret_cast<uint4*>(&sB[0][r * BST + ch + u * 4]) = o;
        }
    }
    __syncthreads();

    for (int kt = 0; kt < 16; kt++) {
        const int cur = kt & 1;

        // issue next tile's loads before MMA (latency hidden under tensor work)
        float4 vn[4];
        if (kt < 15) {
            const int kg = (kt + 1) * 32;
            const float* src = (kg < H_) ? (rowT1 + kg) : (rowT + (kg - H_));
            #pragma unroll
            for (int u = 0; u < 4; u++)
                vn[u] = *reinterpret_cast<const float4*>(src + ch + u * 4);
        }

        const uint32_t* sC = &sB[cur][0];
        #pragma unroll
        for (int ks = 0; ks < 4; ks++) {
            long aIdx = (((long)(nt * 4 + wq) * 64 + kt * 4 + ks) * 2) * 32 + lane;
            uint4 A0 = wpack[aIdx];
            uint4 A1 = wpack[aIdx + 32];

            #pragma unroll
            for (int j = 0; j < 8; j++) {
                int mloc = wm * 64 + j * 8 + (lane >> 2);
                uint32_t b0  = sC[mloc * BST + ks * 8 + (lane & 3)];
                uint32_t b1v = sC[mloc * BST + ks * 8 + (lane & 3) + 4];
                mma_tf32(acc[0][j], A0.x, A0.y, A0.z, A0.w, b0, b1v);
                mma_tf32(acc[1][j], A1.x, A1.y, A1.z, A1.w, b0, b1v);
            }
        }

        if (kt < 15) {
            #pragma unroll
            for (int u = 0; u < 4; u++) {
                uint4 o;
                o.x = f2tf32(vn[u].x); o.y = f2tf32(vn[u].y);
                o.z = f2tf32(vn[u].z); o.w = f2tf32(vn[u].w);
                *reinterpret_cast<uint4*>(&sB[cur ^ 1][r * BST + ch + u * 4]) = o;
            }
        }
        __syncthreads();
    }

    // Epilogue: +b1, relu, tf32-convert, store hT[n][m]
    #pragma unroll
    for (int s = 0; s < 2; s++) {
        int n_g = nt * 128 + wq * 32 + s * 16 + (lane >> 2);
        float bn0 = __ldg(&b1[n_g]);
        float bn8 = __ldg(&b1[n_g + 8]);
        #pragma unroll
        for (int j = 0; j < 8; j++) {
            int m_g = mBase + wm * 64 + j * 8 + (lane & 3) * 2;
            uint2 o0, o8;
            o0.x = f2tf32(fmaxf(acc[s][j][0] + bn0, 0.f));
            o0.y = f2tf32(fmaxf(acc[s][j][1] + bn0, 0.f));
            o8.x = f2tf32(fmaxf(acc[s][j][2] + bn8, 0.f));
            o8.y = f2tf32(fmaxf(acc[s][j][3] + bn8, 0.f));
            *reinterpret_cast<uint2*>(&g_hT[(long)n_g * M1P + m_g])       = o0;
            *reinterpret_cast<uint2*>(&g_hT[(long)(n_g + 8) * M1P + m_g]) = o8;
        }
    }
}

// ===========================================================================
// GEMM2 (tf32 mma.sync, smem-free mainloop): trans = h @ W2 + b2
//   Warp tile: 16(m) x 64(n), K=256 in 32 ktiles.  A direct from g_hT (tf32
//   bits, L2-resident), B from g_w2pack (64KB, L1-resident).
//   Epilogue: smem transpose -> fully coalesced contiguous g_trans store.
// ===========================================================================
__global__ __launch_bounds__(256) void gemm2_tc(const float* __restrict__ b2) {
    __shared__ float sm[128 * 65];

    const int tid  = threadIdx.x;
    const int warp = tid >> 5;
    const int lane = tid & 31;
    const int g = lane >> 2;
    const int t = lane & 3;
    const int m0 = blockIdx.x * 128 + warp * 16;

    float acc[8][4];
    #pragma unroll
    for (int nb = 0; nb < 8; nb++)
        #pragma unroll
        for (int d = 0; d < 4; d++) acc[nb][d] = 0.f;

    const uint2* w2p = reinterpret_cast<const uint2*>(g_w2pack);

    #pragma unroll 4
    for (int kt = 0; kt < 32; kt++) {
        const int k0 = kt * 8;
        uint32_t a0 = g_hT[(long)(k0 + t) * M1P + m0 + g];
        uint32_t a1 = g_hT[(long)(k0 + t) * M1P + m0 + g + 8];
        uint32_t a2 = g_hT[(long)(k0 + t + 4) * M1P + m0 + g];
        uint32_t a3 = g_hT[(long)(k0 + t + 4) * M1P + m0 + g + 8];

        #pragma unroll
        for (int nb = 0; nb < 8; nb++) {
            uint2 bf = __ldg(&w2p[((long)kt * 8 + nb) * 32 + lane]);
            mma_tf32(acc[nb], a0, a1, a2, a3, bf.x, bf.y);
        }
    }

    // stage to smem [m 128][n 64 (pad 65)]
    const int mw = warp * 16;
    #pragma unroll
    for (int nb = 0; nb < 8; nb++) {
        int n = nb * 8 + t * 2;
        sm[(mw + g)     * 65 + n]     = acc[nb][0];
        sm[(mw + g)     * 65 + n + 1] = acc[nb][1];
        sm[(mw + g + 8) * 65 + n]     = acc[nb][2];
        sm[(mw + g + 8) * 65 + n + 1] = acc[nb][3];
    }
    __syncthreads();

    // coalesced contiguous store: 128 rows x 63 = 8064 floats per CTA
    const long base = (long)blockIdx.x * 128 * S_;
    #pragma unroll
    for (int c = 0; c < 32; c++) {
        int idx = c * 256 + tid;
        if (idx < 128 * S_) {
            int mr = idx / S_;
            int n  = idx - mr * S_;
            g_trans[base + idx] = sm[mr * 65 + n] + __ldg(&b2[n]);
        }
    }
}

// ===========================================================================
// Align: softmax over collapsed forward-backward scores. One warp per (b,t).
// ===========================================================================
__global__ __launch_bounds__(256) void align_kernel(
    const float* __restrict__ logits, const int* __restrict__ kw,
    float* __restrict__ out)
{
    const int warp = threadIdx.x >> 5;
    const int lane = threadIdx.x & 31;
    const int r = blockIdx.x * 8 + warp;
    const int b = r / T_;
    const int t = r - b * T_;

    const float* Lb  = logits  + (long)b * T_ * S_;
    const float* Trb = g_trans + (long)b * TM1 * S_;

    const int s0 = lane;
    const int s1 = lane + 32;
    const bool has1 = (s1 < S_);

    float v0, v1;
    if (t == 0) {
        float a0 = Lb[s0];
        float a1 = has1 ? Lb[s1] : -INFINITY;
        float mx = fmaxf(a0, a1);
        #pragma unroll
        for (int o = 16; o > 0; o >>= 1) mx = fmaxf(mx, __shfl_xor_sync(0xffffffff, mx, o));
        float se = __expf(a0 - mx) + (has1 ? __expf(a1 - mx) : 0.f);
        #pragma unroll
        for (int o = 16; o > 0; o >>= 1) se += __shfl_xor_sync(0xffffffff, se, o);
        float lse = mx + __logf(se);
        int k0 = __ldg(&kw[b * 32]);
        float logp0 = Lb[k0] - lse;
        v0 = ((s0 == 0) ? logp0 : 0.f) + Lb[S_ + s0] + Trb[s0];
        v1 = has1 ? (Lb[S_ + s1] + Trb[s1]) : -INFINITY;
    } else if (t == T_ - 1) {
        v0 = Lb[(long)t * S_ + s0] + Trb[(long)(t - 1) * S_ + s0];
        v1 = has1 ? (Lb[(long)t * S_ + s1] + Trb[(long)(t - 1) * S_ + s1]) : -INFINITY;
    } else {
        v0 = Lb[(long)t * S_ + s0] + Lb[(long)(t + 1) * S_ + s0]
           + Trb[(long)(t - 1) * S_ + s0] + Trb[(long)t * S_ + s0];
        v1 = has1 ? (Lb[(long)t * S_ + s1] + Lb[(long)(t + 1) * S_ + s1]
                   + Trb[(long)(t - 1) * S_ + s1] + Trb[(long)t * S_ + s1])
                  : -INFINITY;
    }

    float mx = fmaxf(v0, v1);
    #pragma unroll
    for (int o = 16; o > 0; o >>= 1) mx = fmaxf(mx, __shfl_xor_sync(0xffffffff, mx, o));
    float e0 = expf(v0 - mx);
    float e1 = has1 ? expf(v1 - mx) : 0.f;
    float sum = e0 + e1;
    #pragma unroll
    for (int o = 16; o > 0; o >>= 1) sum += __shfl_xor_sync(0xffffffff, sum, o);
    float inv = 1.f / sum;

    float* ob = out + (long)r * S_;
    ob[s0] = e0 * inv;
    if (has1) ob[s1] = e1 * inv;
}

// ===========================================================================
extern "C" void kernel_launch(void* const* d_in, const int* in_sizes, int n_in,
                              void* d_out, int out_size) {
    const float* logits = (const float*)d_in[0];   // (B,T,S)
    const float* emb    = (const float*)d_in[1];   // (B,T,H)
    const int*   kw     = (const int*)  d_in[2];   // (B,32)
    const float* W1     = (const float*)d_in[3];   // (2H,H)
    const float* b1     = (const float*)d_in[4];   // (H,)
    const float* W2     = (const float*)d_in[5];   // (H,S)
    const float* b2     = (const float*)d_in[6];   // (S,)
    float*       out    = (float*)d_out;           // (B,T,S)

    prep_w1<<<128, 256>>>(W1);
    prep_w2<<<32, 256>>>(W2);
    gemm1_tc<<<dim3(500, 2), 256>>>(emb, b1);
    gemm2_tc<<<500, 256>>>(b2);
    align_kernel<<<(B_ * T_) / 8, 256>>>(logits, kw, out);
}

// round 5
// speedup vs baseline: 3.5293x; 1.2698x over previous
#include <cuda_runtime.h>
#include <cuda_fp16.h>
#include <math.h>
#include <cstdint>

#define B_   32
#define T_   2000
#define H_   256
#define S_   63
#define TM1  1999            // T-1
#define M1   63968           // B*(T-1)
#define M1P  64000           // padded row count
#define K1   512             // 2*H
#define N1   256             // H

// Scratch (device globals: allocation-guard safe)
__device__ __align__(16) __half   g_h16[M1P * N1];       // hidden [m][k], fp16
__device__ __align__(16) float    g_trans[M1P * S_];     // transition scores
__device__ __align__(16) uint4    g_w1pack[16384];       // W1^T fp16 A-frags
__device__ __align__(16) uint2    g_w2pack[4096];        // W2 fp16 B-frags

__device__ __forceinline__ uint32_t h2u(__half2 h) {
    return *reinterpret_cast<uint32_t*>(&h);
}

__device__ __forceinline__ void mma_f16(float* c, uint32_t a0, uint32_t a1,
                                        uint32_t a2, uint32_t a3,
                                        uint32_t b0, uint32_t b1) {
    asm volatile(
        "mma.sync.aligned.m16n8k16.row.col.f32.f16.f16.f32 "
        "{%0,%1,%2,%3}, {%4,%5,%6,%7}, {%8,%9}, {%0,%1,%2,%3};"
        : "+f"(c[0]), "+f"(c[1]), "+f"(c[2]), "+f"(c[3])
        : "r"(a0), "r"(a1), "r"(a2), "r"(a3), "r"(b0), "r"(b1));
}

// ===========================================================================
// Prep W1: pack W1^T into per-lane fp16 A-fragment order (m16n8k16).
//   idx = ((((nt*4+q)*32 + kstep)*2 + s)*32 + lane)
//   n0 = nt*128 + q*32 + s*16 + lane/4,  k0 = kstep*16 + (lane%4)*2
//   a0={W1T[n0][k0],[k0+1]} a1=n0+8  a2=k0+8  a3=both
// ===========================================================================
__global__ __launch_bounds__(256) void prep_w1(const float* __restrict__ W1) {
    int idx   = blockIdx.x * 256 + threadIdx.x;   // 0..16383
    int lane  = idx & 31;
    int s     = (idx >> 5) & 1;
    int kstep = (idx >> 6) & 31;
    int q     = (idx >> 11) & 3;
    int nt    = (idx >> 13) & 1;

    int n0 = nt * 128 + q * 32 + s * 16 + (lane >> 2);
    int k0 = kstep * 16 + (lane & 3) * 2;

    // W1T[n][k] = W1[k*256+n]
    uint4 o;
    o.x = h2u(__floats2half2_rn(W1[(long)k0 * N1 + n0],       W1[(long)(k0 + 1) * N1 + n0]));
    o.y = h2u(__floats2half2_rn(W1[(long)k0 * N1 + n0 + 8],   W1[(long)(k0 + 1) * N1 + n0 + 8]));
    o.z = h2u(__floats2half2_rn(W1[(long)(k0 + 8) * N1 + n0],     W1[(long)(k0 + 9) * N1 + n0]));
    o.w = h2u(__floats2half2_rn(W1[(long)(k0 + 8) * N1 + n0 + 8], W1[(long)(k0 + 9) * N1 + n0 + 8]));
    g_w1pack[idx] = o;
}

// ===========================================================================
// Prep W2: pack W2 [K=256][S=63] into per-lane fp16 B-fragment order.
//   idx = (kt*8 + nb)*32 + lane ; k = kt*16+(lane%4)*2, n = nb*8+lane/4
//   b0 = {W2[k][n], W2[k+1][n]},  b1 = {W2[k+8][n], W2[k+9][n]}
// ===========================================================================
__global__ __launch_bounds__(256) void prep_w2(const float* __restrict__ W2) {
    int idx  = blockIdx.x * 256 + threadIdx.x;   // 0..4095
    int lane = idx & 31;
    int nb   = (idx >> 5) & 7;
    int kt   = idx >> 8;
    int k = kt * 16 + (lane & 3) * 2;
    int n = nb * 8 + (lane >> 2);
    float w00 = (n < S_) ? W2[(long)k * S_ + n]       : 0.f;
    float w01 = (n < S_) ? W2[(long)(k + 1) * S_ + n] : 0.f;
    float w10 = (n < S_) ? W2[(long)(k + 8) * S_ + n] : 0.f;
    float w11 = (n < S_) ? W2[(long)(k + 9) * S_ + n] : 0.f;
    uint2 o;
    o.x = h2u(__floats2half2_rn(w00, w01));
    o.y = h2u(__floats2half2_rn(w10, w11));
    g_w2pack[idx] = o;
}

// ===========================================================================
// GEMM1 (fp16 mma.sync m16n8k16, double-buffered):
//   hT = relu(W1^T @ pairs^T + b1); output stored as fp16 h[m][k] row-major.
//   CTA tile 128(hid) x 128(m); warp tile 32(hid) x 64(m); K=512, ktile=32.
//   smem: B double-buffer (stride 40 halfs -> conflict-free) aliased with
//   epilogue transpose staging.
// ===========================================================================
#define BSTW 20   // uint32 words per B row (40 halfs)
__global__ __launch_bounds__(256, 2) void gemm1_tc(
    const float* __restrict__ emb, const float* __restrict__ b1)
{
    extern __shared__ __align__(16) char dynsm[];
    uint32_t* sB0 = reinterpret_cast<uint32_t*>(dynsm);            // [2][128*20]
    __half*   sT  = reinterpret_cast<__half*>(dynsm);              // [128][136] (epilogue)

    const int tid  = threadIdx.x;
    const int warp = tid >> 5;
    const int lane = tid & 31;
    const int g    = lane >> 2;
    const int t    = lane & 3;
    const int wq   = warp & 3;     // hidden 32-block
    const int wm   = warp >> 2;    // m 64-block
    const int mBase = blockIdx.x * 128;
    const int nt    = blockIdx.y;

    // B-stage mapping: thread handles row r, 16 k-values
    const int r  = tid >> 1;
    const int ch = (tid & 1) * 16;
    int m = mBase + r;
    if (m >= M1) m = M1 - 1;
    const int b = m / TM1;
    const int tt = m - b * TM1;
    const float* rowT  = emb + ((long)b * T_ + tt) * H_;   // pairs k>=256
    const float* rowT1 = rowT + H_;                        // pairs k<256

    float acc[2][8][4];
    #pragma unroll
    for (int s = 0; s < 2; s++)
        #pragma unroll
        for (int j = 0; j < 8; j++)
            #pragma unroll
            for (int d = 0; d < 4; d++) acc[s][j][d] = 0.f;

    // prologue: stage kt=0
    {
        #pragma unroll
        for (int u = 0; u < 2; u++) {
            float4 v0 = *reinterpret_cast<const float4*>(rowT1 + ch + u * 8);
            float4 v1 = *reinterpret_cast<const float4*>(rowT1 + ch + u * 8 + 4);
            uint4 o;
            o.x = h2u(__floats2half2_rn(v0.x, v0.y));
            o.y = h2u(__floats2half2_rn(v0.z, v0.w));
            o.z = h2u(__floats2half2_rn(v1.x, v1.y));
            o.w = h2u(__floats2half2_rn(v1.z, v1.w));
            *reinterpret_cast<uint4*>(&sB0[r * BSTW + ch / 2 + u * 4]) = o;
        }
    }
    __syncthreads();

    for (int kt = 0; kt < 16; kt++) {
        const int cur = kt & 1;
        const uint32_t* sC = sB0 + cur * (128 * BSTW);

        // prefetch next tile's global loads
        float4 vn[4];
        if (kt < 15) {
            const int kg = (kt + 1) * 32;
            const float* src = (kg < H_) ? (rowT1 + kg) : (rowT + (kg - H_));
            #pragma unroll
            for (int u = 0; u < 4; u++)
                vn[u] = *reinterpret_cast<const float4*>(src + ch + u * 4);
        }

        #pragma unroll
        for (int ks = 0; ks < 2; ks++) {
            long aIdx = (((long)((nt * 4 + wq) * 32 + kt * 2 + ks)) * 2) * 32 + lane;
            uint4 A0 = g_w1pack[aIdx];
            uint4 A1 = g_w1pack[aIdx + 32];

            #pragma unroll
            for (int j = 0; j < 8; j++) {
                int mloc = wm * 64 + j * 8 + g;
                uint32_t b0v = sC[mloc * BSTW + ks * 8 + t];
                uint32_t b1v = sC[mloc * BSTW + ks * 8 + t + 4];
                mma_f16(acc[0][j], A0.x, A0.y, A0.z, A0.w, b0v, b1v);
                mma_f16(acc[1][j], A1.x, A1.y, A1.z, A1.w, b0v, b1v);
            }
        }

        if (kt < 15) {
            uint32_t* sN = sB0 + (cur ^ 1) * (128 * BSTW);
            #pragma unroll
            for (int u = 0; u < 2; u++) {
                uint4 o;
                o.x = h2u(__floats2half2_rn(vn[u * 2].x,     vn[u * 2].y));
                o.y = h2u(__floats2half2_rn(vn[u * 2].z,     vn[u * 2].w));
                o.z = h2u(__floats2half2_rn(vn[u * 2 + 1].x, vn[u * 2 + 1].y));
                o.w = h2u(__floats2half2_rn(vn[u * 2 + 1].z, vn[u * 2 + 1].w));
                *reinterpret_cast<uint4*>(&sN[r * BSTW + ch / 2 + u * 4]) = o;
            }
        }
        __syncthreads();
    }

    // Epilogue: +b1, relu, fp16, transpose via smem -> coalesced h[m][k] store
    #pragma unroll
    for (int s = 0; s < 2; s++) {
        int n_loc = wq * 32 + s * 16 + g;
        float bn0 = __ldg(&b1[nt * 128 + n_loc]);
        float bn8 = __ldg(&b1[nt * 128 + n_loc + 8]);
        #pragma unroll
        for (int j = 0; j < 8; j++) {
            int m_loc = wm * 64 + j * 8 + t * 2;
            sT[m_loc * 136 + n_loc]           = __float2half(fmaxf(acc[s][j][0] + bn0, 0.f));
            sT[(m_loc + 1) * 136 + n_loc]     = __float2half(fmaxf(acc[s][j][1] + bn0, 0.f));
            sT[m_loc * 136 + n_loc + 8]       = __float2half(fmaxf(acc[s][j][2] + bn8, 0.f));
            sT[(m_loc + 1) * 136 + n_loc + 8] = __float2half(fmaxf(acc[s][j][3] + bn8, 0.f));
        }
    }
    __syncthreads();

    {
        const int row  = tid >> 1;
        const int half = (tid & 1) * 64;
        __half* dst = g_h16 + (long)(mBase + row) * N1 + nt * 128 + half;
        const __half* srcp = &sT[row * 136 + half];
        #pragma unroll
        for (int u = 0; u < 8; u++)
            *reinterpret_cast<uint4*>(dst + u * 8) =
                *reinterpret_cast<const uint4*>(srcp + u * 8);
    }
}

// ===========================================================================
// GEMM2 (fp16 mma.sync, smem-free mainloop): trans = h @ W2 + b2
//   Warp tile 32(m) x 64(n); CTA 256(m); K=256 in 16 ktiles; grid 250.
//   A direct from g_h16 [m][k] fp16 (L2), B from g_w2pack (32KB, L1).
//   Epilogue: smem transpose -> fully coalesced contiguous g_trans store.
// ===========================================================================
__global__ __launch_bounds__(256, 2) void gemm2_tc(const float* __restrict__ b2) {
    extern __shared__ __align__(16) float sm2[];   // [256][65]

    const int tid  = threadIdx.x;
    const int warp = tid >> 5;
    const int lane = tid & 31;
    const int g = lane >> 2;
    const int t = lane & 3;
    const int m0 = blockIdx.x * 256 + warp * 32;

    float acc[2][8][4];
    #pragma unroll
    for (int mf = 0; mf < 2; mf++)
        #pragma unroll
        for (int nb = 0; nb < 8; nb++)
            #pragma unroll
            for (int d = 0; d < 4; d++) acc[mf][nb][d] = 0.f;

    #pragma unroll 2
    for (int kt = 0; kt < 16; kt++) {
        const int k0 = kt * 16 + t * 2;
        uint32_t A[2][4];
        #pragma unroll
        for (int mf = 0; mf < 2; mf++) {
            const __half* r0 = g_h16 + (long)(m0 + mf * 16 + g) * N1;
            const __half* r8 = r0 + 8 * N1;
            A[mf][0] = *reinterpret_cast<const uint32_t*>(r0 + k0);
            A[mf][1] = *reinterpret_cast<const uint32_t*>(r8 + k0);
            A[mf][2] = *reinterpret_cast<const uint32_t*>(r0 + k0 + 8);
            A[mf][3] = *reinterpret_cast<const uint32_t*>(r8 + k0 + 8);
        }
        #pragma unroll
        for (int nb = 0; nb < 8; nb++) {
            uint2 bf = __ldg(&g_w2pack[((long)kt * 8 + nb) * 32 + lane]);
            mma_f16(acc[0][nb], A[0][0], A[0][1], A[0][2], A[0][3], bf.x, bf.y);
            mma_f16(acc[1][nb], A[1][0], A[1][1], A[1][2], A[1][3], bf.x, bf.y);
        }
    }

    // stage to smem [m 256][n 64 (pad 65)]
    #pragma unroll
    for (int mf = 0; mf < 2; mf++) {
        int mr = warp * 32 + mf * 16 + g;
        #pragma unroll
        for (int nb = 0; nb < 8; nb++) {
            int n = nb * 8 + t * 2;
            sm2[mr * 65 + n]           = acc[mf][nb][0];
            sm2[mr * 65 + n + 1]       = acc[mf][nb][1];
            sm2[(mr + 8) * 65 + n]     = acc[mf][nb][2];
            sm2[(mr + 8) * 65 + n + 1] = acc[mf][nb][3];
        }
    }
    __syncthreads();

    // coalesced contiguous store: 256 rows x 63 = 16128 floats per CTA
    const long base = (long)blockIdx.x * 256 * S_;
    #pragma unroll
    for (int c = 0; c < 63; c++) {
        int idx = c * 256 + tid;
        int mr = idx / S_;
        int n  = idx - mr * S_;
        g_trans[base + idx] = sm2[mr * 65 + n] + __ldg(&b2[n]);
    }
}

// ===========================================================================
// Align: softmax over collapsed forward-backward scores. One warp per (b,t).
// ===========================================================================
__global__ __launch_bounds__(256) void align_kernel(
    const float* __restrict__ logits, const int* __restrict__ kw,
    float* __restrict__ out)
{
    const int warp = threadIdx.x >> 5;
    const int lane = threadIdx.x & 31;
    const int r = blockIdx.x * 8 + warp;
    const int b = r / T_;
    const int t = r - b * T_;

    const float* Lb  = logits  + (long)b * T_ * S_;
    const float* Trb = g_trans + (long)b * TM1 * S_;

    const int s0 = lane;
    const int s1 = lane + 32;
    const bool has1 = (s1 < S_);

    float v0, v1;
    if (t == 0) {
        float a0 = Lb[s0];
        float a1 = has1 ? Lb[s1] : -INFINITY;
        float mx = fmaxf(a0, a1);
        #pragma unroll
        for (int o = 16; o > 0; o >>= 1) mx = fmaxf(mx, __shfl_xor_sync(0xffffffff, mx, o));
        float se = __expf(a0 - mx) + (has1 ? __expf(a1 - mx) : 0.f);
        #pragma unroll
        for (int o = 16; o > 0; o >>= 1) se += __shfl_xor_sync(0xffffffff, se, o);
        float lse = mx + __logf(se);
        int k0 = __ldg(&kw[b * 32]);
        float logp0 = Lb[k0] - lse;
        v0 = ((s0 == 0) ? logp0 : 0.f) + Lb[S_ + s0] + Trb[s0];
        v1 = has1 ? (Lb[S_ + s1] + Trb[s1]) : -INFINITY;
    } else if (t == T_ - 1) {
        v0 = Lb[(long)t * S_ + s0] + Trb[(long)(t - 1) * S_ + s0];
        v1 = has1 ? (Lb[(long)t * S_ + s1] + Trb[(long)(t - 1) * S_ + s1]) : -INFINITY;
    } else {
        v0 = Lb[(long)t * S_ + s0] + Lb[(long)(t + 1) * S_ + s0]
           + Trb[(long)(t - 1) * S_ + s0] + Trb[(long)t * S_ + s0];
        v1 = has1 ? (Lb[(long)t * S_ + s1] + Lb[(long)(t + 1) * S_ + s1]
                   + Trb[(long)(t - 1) * S_ + s1] + Trb[(long)t * S_ + s1])
                  : -INFINITY;
    }

    float mx = fmaxf(v0, v1);
    #pragma unroll
    for (int o = 16; o > 0; o >>= 1) mx = fmaxf(mx, __shfl_xor_sync(0xffffffff, mx, o));
    float e0 = expf(v0 - mx);
    float e1 = has1 ? expf(v1 - mx) : 0.f;
    float sum = e0 + e1;
    #pragma unroll
    for (int o = 16; o > 0; o >>= 1) sum += __shfl_xor_sync(0xffffffff, sum, o);
    float inv = 1.f / sum;

    float* ob = out + (long)r * S_;
    ob[s0] = e0 * inv;
    if (has1) ob[s1] = e1 * inv;
}

// ===========================================================================
extern "C" void kernel_launch(void* const* d_in, const int* in_sizes, int n_in,
                              void* d_out, int out_size) {
    const float* logits = (const float*)d_in[0];   // (B,T,S)
    const float* emb    = (const float*)d_in[1];   // (B,T,H)
    const int*   kw     = (const int*)  d_in[2];   // (B,32)
    const float* W1     = (const float*)d_in[3];   // (2H,H)
    const float* b1     = (const float*)d_in[4];   // (H,)
    const float* W2     = (const float*)d_in[5];   // (H,S)
    const float* b2     = (const float*)d_in[6];   // (S,)
    float*       out    = (float*)d_out;           // (B,T,S)

    const int smem1 = 128 * 136 * 2;       // 34816 (>= 2*128*20*4 = 20480)
    const int smem2 = 256 * 65 * 4;        // 66560
    cudaFuncSetAttribute(gemm1_tc, cudaFuncAttributeMaxDynamicSharedMemorySize, smem1);
    cudaFuncSetAttribute(gemm2_tc, cudaFuncAttributeMaxDynamicSharedMemorySize, smem2);

    prep_w1<<<64, 256>>>(W1);
    prep_w2<<<16, 256>>>(W2);
    gemm1_tc<<<dim3(500, 2), 256, smem1>>>(emb, b1);
    gemm2_tc<<<250, 256, smem2>>>(b2);
    align_kernel<<<(B_ * T_) / 8, 256>>>(logits, kw, out);
}

// round 6
// speedup vs baseline: 3.7036x; 1.0494x over previous
#include <cuda_runtime.h>
#include <cuda_fp16.h>
#include <math.h>
#include <cstdint>

#define B_   32
#define T_   2000
#define H_   256
#define S_   63
#define TM1  1999            // T-1
#define M1   63968           // B*(T-1)
#define M1P  64000           // padded row count
#define K1   512             // 2*H
#define N1   256             // H

// Scratch (device globals: allocation-guard safe)
__device__ __align__(16) __half   g_h16[M1P * N1];       // hidden [m][k], fp16
__device__ __align__(16) float    g_trans[M1P * S_];     // transition scores
__device__ __align__(16) uint4    g_w1pack[16384];       // W1^T fp16 A-frags
__device__ __align__(16) uint2    g_w2pack[4096];        // W2 fp16 B-frags

__device__ __forceinline__ uint32_t h2u(__half2 h) {
    return *reinterpret_cast<uint32_t*>(&h);
}

__device__ __forceinline__ void mma_f16(float* c, uint32_t a0, uint32_t a1,
                                        uint32_t a2, uint32_t a3,
                                        uint32_t b0, uint32_t b1) {
    asm volatile(
        "mma.sync.aligned.m16n8k16.row.col.f32.f16.f16.f32 "
        "{%0,%1,%2,%3}, {%4,%5,%6,%7}, {%8,%9}, {%0,%1,%2,%3};"
        : "+f"(c[0]), "+f"(c[1]), "+f"(c[2]), "+f"(c[3])
        : "r"(a0), "r"(a1), "r"(a2), "r"(a3), "r"(b0), "r"(b1));
}

// ===========================================================================
// Prep W1: pack W1^T into per-lane fp16 A-fragment order (m16n8k16).
//   idx = ((q*32 + kstep)*2 + s)*32 + lane,  q in 0..7
//   n0 = q*32 + s*16 + lane/4,  k0 = kstep*16 + (lane%4)*2
// ===========================================================================
__global__ __launch_bounds__(256) void prep_w1(const float* __restrict__ W1) {
    int idx   = blockIdx.x * 256 + threadIdx.x;   // 0..16383
    int lane  = idx & 31;
    int s     = (idx >> 5) & 1;
    int kstep = (idx >> 6) & 31;
    int q     = (idx >> 11) & 7;

    int n0 = q * 32 + s * 16 + (lane >> 2);
    int k0 = kstep * 16 + (lane & 3) * 2;

    // W1T[n][k] = W1[k*256+n]
    uint4 o;
    o.x = h2u(__floats2half2_rn(W1[(long)k0 * N1 + n0],       W1[(long)(k0 + 1) * N1 + n0]));
    o.y = h2u(__floats2half2_rn(W1[(long)k0 * N1 + n0 + 8],   W1[(long)(k0 + 1) * N1 + n0 + 8]));
    o.z = h2u(__floats2half2_rn(W1[(long)(k0 + 8) * N1 + n0],     W1[(long)(k0 + 9) * N1 + n0]));
    o.w = h2u(__floats2half2_rn(W1[(long)(k0 + 8) * N1 + n0 + 8], W1[(long)(k0 + 9) * N1 + n0 + 8]));
    g_w1pack[idx] = o;
}

// ===========================================================================
// Prep W2: pack W2 [K=256][S=63] into per-lane fp16 B-fragment order.
// ===========================================================================
__global__ __launch_bounds__(256) void prep_w2(const float* __restrict__ W2) {
    int idx  = blockIdx.x * 256 + threadIdx.x;   // 0..4095
    int lane = idx & 31;
    int nb   = (idx >> 5) & 7;
    int kt   = idx >> 8;
    int k = kt * 16 + (lane & 3) * 2;
    int n = nb * 8 + (lane >> 2);
    float w00 = (n < S_) ? W2[(long)k * S_ + n]       : 0.f;
    float w01 = (n < S_) ? W2[(long)(k + 1) * S_ + n] : 0.f;
    float w10 = (n < S_) ? W2[(long)(k + 8) * S_ + n] : 0.f;
    float w11 = (n < S_) ? W2[(long)(k + 9) * S_ + n] : 0.f;
    uint2 o;
    o.x = h2u(__floats2half2_rn(w00, w01));
    o.y = h2u(__floats2half2_rn(w10, w11));
    g_w2pack[idx] = o;
}

// ===========================================================================
// GEMM1 (fp16 mma.sync, full-N CTA): h = relu(pairs @ W1 + b1) as fp16 [m][k]
//   CTA tile 256(hid) x 128(m), 512 threads = 16 warps (8 nb x 2 mb).
//   K=512, ktile=32, double-buffered smem B; emb read exactly ONCE.
// ===========================================================================
#define BSTW 20   // uint32 words per B row (40 halfs: 32 data + 8 pad)
__global__ __launch_bounds__(512, 1) void gemm1_tc(
    const float* __restrict__ emb, const float* __restrict__ b1)
{
    extern __shared__ __align__(16) char dynsm[];
    uint32_t* sB0 = reinterpret_cast<uint32_t*>(dynsm);   // [2][128*20] mainloop
    __half*   sT  = reinterpret_cast<__half*>(dynsm);     // [128][264] epilogue

    const int tid  = threadIdx.x;
    const int warp = tid >> 5;
    const int lane = tid & 31;
    const int g    = lane >> 2;
    const int t    = lane & 3;
    const int wq   = warp & 7;     // hidden 32-block (0..7)
    const int wm   = warp >> 3;    // m 64-block (0..1)
    const int mBase = blockIdx.x * 128;

    // B-stage mapping: 4 threads per row, 8 k-values each
    const int r  = tid >> 2;             // 0..127
    const int ch = (tid & 3) * 8;        // 0,8,16,24
    int m = mBase + r;
    if (m >= M1) m = M1 - 1;
    const int b = m / TM1;
    const int tt = m - b * TM1;
    const float* rowT  = emb + ((long)b * T_ + tt) * H_;   // pairs k>=256
    const float* rowT1 = rowT + H_;                        // pairs k<256

    float acc[2][8][4];
    #pragma unroll
    for (int s = 0; s < 2; s++)
        #pragma unroll
        for (int j = 0; j < 8; j++)
            #pragma unroll
            for (int d = 0; d < 4; d++) acc[s][j][d] = 0.f;

    // prologue: stage kt=0 (kg=0 < H_)
    {
        float4 v0 = *reinterpret_cast<const float4*>(rowT1 + ch);
        float4 v1 = *reinterpret_cast<const float4*>(rowT1 + ch + 4);
        uint4 o;
        o.x = h2u(__floats2half2_rn(v0.x, v0.y));
        o.y = h2u(__floats2half2_rn(v0.z, v0.w));
        o.z = h2u(__floats2half2_rn(v1.x, v1.y));
        o.w = h2u(__floats2half2_rn(v1.z, v1.w));
        *reinterpret_cast<uint4*>(&sB0[r * BSTW + ch / 2]) = o;
    }
    __syncthreads();

    for (int kt = 0; kt < 16; kt++) {
        const int cur = kt & 1;
        const uint32_t* sC = sB0 + cur * (128 * BSTW);

        // prefetch next tile's global loads (latency hidden under MMAs)
        float4 vn0, vn1;
        if (kt < 15) {
            const int kg = (kt + 1) * 32;
            const float* src = (kg < H_) ? (rowT1 + kg) : (rowT + (kg - H_));
            vn0 = *reinterpret_cast<const float4*>(src + ch);
            vn1 = *reinterpret_cast<const float4*>(src + ch + 4);
        }

        #pragma unroll
        for (int ks = 0; ks < 2; ks++) {
            long aIdx = (((long)(wq * 32 + kt * 2 + ks)) * 2) * 32 + lane;
            uint4 A0 = g_w1pack[aIdx];        // s=0: n0, n0+8
            uint4 A1 = g_w1pack[aIdx + 32];   // s=1: n0+16, n0+24

            #pragma unroll
            for (int j = 0; j < 8; j++) {
                int mloc = wm * 64 + j * 8 + g;
                uint32_t b0v = sC[mloc * BSTW + ks * 8 + t];
                uint32_t b1v = sC[mloc * BSTW + ks * 8 + t + 4];
                mma_f16(acc[0][j], A0.x, A0.y, A0.z, A0.w, b0v, b1v);
                mma_f16(acc[1][j], A1.x, A1.y, A1.z, A1.w, b0v, b1v);
            }
        }

        if (kt < 15) {
            uint32_t* sN = sB0 + (cur ^ 1) * (128 * BSTW);
            uint4 o;
            o.x = h2u(__floats2half2_rn(vn0.x, vn0.y));
            o.y = h2u(__floats2half2_rn(vn0.z, vn0.w));
            o.z = h2u(__floats2half2_rn(vn1.x, vn1.y));
            o.w = h2u(__floats2half2_rn(vn1.z, vn1.w));
            *reinterpret_cast<uint4*>(&sN[r * BSTW + ch / 2]) = o;
        }
        __syncthreads();
    }

    // Epilogue: +b1, relu, fp16, transpose via smem -> coalesced h[m][k] store
    #pragma unroll
    for (int s = 0; s < 2; s++) {
        int n_g = wq * 32 + s * 16 + g;
        float bn0 = __ldg(&b1[n_g]);
        float bn8 = __ldg(&b1[n_g + 8]);
        #pragma unroll
        for (int j = 0; j < 8; j++) {
            int m_loc = wm * 64 + j * 8 + t * 2;
            sT[m_loc * 264 + n_g]           = __float2half(fmaxf(acc[s][j][0] + bn0, 0.f));
            sT[(m_loc + 1) * 264 + n_g]     = __float2half(fmaxf(acc[s][j][1] + bn0, 0.f));
            sT[m_loc * 264 + n_g + 8]       = __float2half(fmaxf(acc[s][j][2] + bn8, 0.f));
            sT[(m_loc + 1) * 264 + n_g + 8] = __float2half(fmaxf(acc[s][j][3] + bn8, 0.f));
        }
    }
    __syncthreads();

    {
        const int row = tid >> 2;             // 0..127
        const int seg = (tid & 3) * 64;       // 64 halfs per thread
        __half* dst = g_h16 + (long)(mBase + row) * N1 + seg;
        const __half* srcp = &sT[row * 264 + seg];
        #pragma unroll
        for (int u = 0; u < 8; u++)
            *reinterpret_cast<uint4*>(dst + u * 8) =
                *reinterpret_cast<const uint4*>(srcp + u * 8);
    }
}

// ===========================================================================
// GEMM2 (fp16 mma.sync, smem-free pipelined mainloop): trans = h @ W2 + b2
//   Warp tile 32(m) x 64(n); CTA 256(m); K=256 in 16 ktiles; grid 250.
// ===========================================================================
__global__ __launch_bounds__(256, 2) void gemm2_tc(const float* __restrict__ b2) {
    extern __shared__ __align__(16) float sm2[];   // [256][65]

    const int tid  = threadIdx.x;
    const int warp = tid >> 5;
    const int lane = tid & 31;
    const int g = lane >> 2;
    const int t = lane & 3;
    const int m0 = blockIdx.x * 256 + warp * 32;

    float acc[2][8][4];
    #pragma unroll
    for (int mf = 0; mf < 2; mf++)
        #pragma unroll
        for (int nb = 0; nb < 8; nb++)
            #pragma unroll
            for (int d = 0; d < 4; d++) acc[mf][nb][d] = 0.f;

    const __half* rbase0 = g_h16 + (long)(m0 + g) * N1;
    const __half* rbase1 = g_h16 + (long)(m0 + 16 + g) * N1;

    // software pipeline: prefetch kt=0
    uint32_t A[2][4];
    {
        const int k0 = t * 2;
        A[0][0] = *reinterpret_cast<const uint32_t*>(rbase0 + k0);
        A[0][1] = *reinterpret_cast<const uint32_t*>(rbase0 + 8 * N1 + k0);
        A[0][2] = *reinterpret_cast<const uint32_t*>(rbase0 + k0 + 8);
        A[0][3] = *reinterpret_cast<const uint32_t*>(rbase0 + 8 * N1 + k0 + 8);
        A[1][0] = *reinterpret_cast<const uint32_t*>(rbase1 + k0);
        A[1][1] = *reinterpret_cast<const uint32_t*>(rbase1 + 8 * N1 + k0);
        A[1][2] = *reinterpret_cast<const uint32_t*>(rbase1 + k0 + 8);
        A[1][3] = *reinterpret_cast<const uint32_t*>(rbase1 + 8 * N1 + k0 + 8);
    }

    #pragma unroll
    for (int kt = 0; kt < 16; kt++) {
        uint32_t An[2][4];
        if (kt < 15) {
            const int k0 = (kt + 1) * 16 + t * 2;
            An[0][0] = *reinterpret_cast<const uint32_t*>(rbase0 + k0);
            An[0][1] = *reinterpret_cast<const uint32_t*>(rbase0 + 8 * N1 + k0);
            An[0][2] = *reinterpret_cast<const uint32_t*>(rbase0 + k0 + 8);
            An[0][3] = *reinterpret_cast<const uint32_t*>(rbase0 + 8 * N1 + k0 + 8);
            An[1][0] = *reinterpret_cast<const uint32_t*>(rbase1 + k0);
            An[1][1] = *reinterpret_cast<const uint32_t*>(rbase1 + 8 * N1 + k0);
            An[1][2] = *reinterpret_cast<const uint32_t*>(rbase1 + k0 + 8);
            An[1][3] = *reinterpret_cast<const uint32_t*>(rbase1 + 8 * N1 + k0 + 8);
        }

        #pragma unroll
        for (int nb = 0; nb < 8; nb++) {
            uint2 bf = __ldg(&g_w2pack[((long)kt * 8 + nb) * 32 + lane]);
            mma_f16(acc[0][nb], A[0][0], A[0][1], A[0][2], A[0][3], bf.x, bf.y);
            mma_f16(acc[1][nb], A[1][0], A[1][1], A[1][2], A[1][3], bf.x, bf.y);
        }

        if (kt < 15) {
            #pragma unroll
            for (int mf = 0; mf < 2; mf++)
                #pragma unroll
                for (int d = 0; d < 4; d++) A[mf][d] = An[mf][d];
        }
    }

    // stage to smem [m 256][n 64 (pad 65)]
    #pragma unroll
    for (int mf = 0; mf < 2; mf++) {
        int mr = warp * 32 + mf * 16 + g;
        #pragma unroll
        for (int nb = 0; nb < 8; nb++) {
            int n = nb * 8 + t * 2;
            sm2[mr * 65 + n]           = acc[mf][nb][0];
            sm2[mr * 65 + n + 1]       = acc[mf][nb][1];
            sm2[(mr + 8) * 65 + n]     = acc[mf][nb][2];
            sm2[(mr + 8) * 65 + n + 1] = acc[mf][nb][3];
        }
    }
    __syncthreads();

    // coalesced contiguous store: 256 rows x 63 = 16128 floats per CTA
    const long base = (long)blockIdx.x * 256 * S_;
    #pragma unroll
    for (int c = 0; c < 63; c++) {
        int idx = c * 256 + tid;
        int mr = idx / S_;
        int n  = idx - mr * S_;
        g_trans[base + idx] = sm2[mr * 65 + n] + __ldg(&b2[n]);
    }
}

// ===========================================================================
// Align: softmax over collapsed forward-backward scores. One warp per (b,t).
// ===========================================================================
__global__ __launch_bounds__(256) void align_kernel(
    const float* __restrict__ logits, const int* __restrict__ kw,
    float* __restrict__ out)
{
    const int warp = threadIdx.x >> 5;
    const int lane = threadIdx.x & 31;
    const int r = blockIdx.x * 8 + warp;
    const int b = r / T_;
    const int t = r - b * T_;

    const float* Lb  = logits  + (long)b * T_ * S_;
    const float* Trb = g_trans + (long)b * TM1 * S_;

    const int s0 = lane;
    const int s1 = lane + 32;
    const bool has1 = (s1 < S_);

    float v0, v1;
    if (t == 0) {
        float a0 = Lb[s0];
        float a1 = has1 ? Lb[s1] : -INFINITY;
        float mx = fmaxf(a0, a1);
        #pragma unroll
        for (int o = 16; o > 0; o >>= 1) mx = fmaxf(mx, __shfl_xor_sync(0xffffffff, mx, o));
        float se = __expf(a0 - mx) + (has1 ? __expf(a1 - mx) : 0.f);
        #pragma unroll
        for (int o = 16; o > 0; o >>= 1) se += __shfl_xor_sync(0xffffffff, se, o);
        float lse = mx + __logf(se);
        int k0 = __ldg(&kw[b * 32]);
        float logp0 = Lb[k0] - lse;
        v0 = ((s0 == 0) ? logp0 : 0.f) + Lb[S_ + s0] + Trb[s0];
        v1 = has1 ? (Lb[S_ + s1] + Trb[s1]) : -INFINITY;
    } else if (t == T_ - 1) {
        v0 = Lb[(long)t * S_ + s0] + Trb[(long)(t - 1) * S_ + s0];
        v1 = has1 ? (Lb[(long)t * S_ + s1] + Trb[(long)(t - 1) * S_ + s1]) : -INFINITY;
    } else {
        v0 = Lb[(long)t * S_ + s0] + Lb[(long)(t + 1) * S_ + s0]
           + Trb[(long)(t - 1) * S_ + s0] + Trb[(long)t * S_ + s0];
        v1 = has1 ? (Lb[(long)t * S_ + s1] + Lb[(long)(t + 1) * S_ + s1]
                   + Trb[(long)(t - 1) * S_ + s1] + Trb[(long)t * S_ + s1])
                  : -INFINITY;
    }

    float mx = fmaxf(v0, v1);
    #pragma unroll
    for (int o = 16; o > 0; o >>= 1) mx = fmaxf(mx, __shfl_xor_sync(0xffffffff, mx, o));
    float e0 = expf(v0 - mx);
    float e1 = has1 ? expf(v1 - mx) : 0.f;
    float sum = e0 + e1;
    #pragma unroll
    for (int o = 16; o > 0; o >>= 1) sum += __shfl_xor_sync(0xffffffff, sum, o);
    float inv = 1.f / sum;

    float* ob = out + (long)r * S_;
    ob[s0] = e0 * inv;
    if (has1) ob[s1] = e1 * inv;
}

// ===========================================================================
extern "C" void kernel_launch(void* const* d_in, const int* in_sizes, int n_in,
                              void* d_out, int out_size) {
    const float* logits = (const float*)d_in[0];   // (B,T,S)
    const float* emb    = (const float*)d_in[1];   // (B,T,H)
    const int*   kw     = (const int*)  d_in[2];   // (B,32)
    const float* W1     = (const float*)d_in[3];   // (2H,H)
    const float* b1     = (const float*)d_in[4];   // (H,)
    const float* W2     = (const float*)d_in[5];   // (H,S)
    const float* b2     = (const float*)d_in[6];   // (S,)
    float*       out    = (float*)d_out;           // (B,T,S)

    const int smem1 = 128 * 264 * 2;       // 67584 (>= 2*128*20*4 = 20480)
    const int smem2 = 256 * 65 * 4;        // 66560
    cudaFuncSetAttribute(gemm1_tc, cudaFuncAttributeMaxDynamicSharedMemorySize, smem1);
    cudaFuncSetAttribute(gemm2_tc, cudaFuncAttributeMaxDynamicSharedMemorySize, smem2);

    prep_w1<<<64, 256>>>(W1);
    prep_w2<<<16, 256>>>(W2);
    gemm1_tc<<<500, 512, smem1>>>(emb, b1);
    gemm2_tc<<<250, 256, smem2>>>(b2);
    align_kernel<<<(B_ * T_) / 8, 256>>>(logits, kw, out);
}

// round 7
// speedup vs baseline: 4.0676x; 1.0983x over previous
#include <cuda_runtime.h>
#include <cuda_fp16.h>
#include <math.h>
#include <cstdint>

#define B_   32
#define T_   2000
#define H_   256
#define S_   63
#define TM1  1999            // T-1
#define M1   63968           // B*(T-1)
#define M1P  64000           // padded row count
#define K1   512             // 2*H
#define N1   256             // H

// Scratch (device globals: allocation-guard safe)
__device__ __align__(16) uint4    g_hfrag[4000 * 16 * 32]; // h fp16, gemm2 A-frag packed
__device__ __align__(16) float    g_trans[M1P * S_];       // transition scores
__device__ __align__(16) uint4    g_w1pack[16384];         // W1^T fp16 A-frags
__device__ __align__(16) uint2    g_w2pack[4096];          // W2 fp16 B-frags

__device__ __forceinline__ uint32_t h2u(__half2 h) {
    return *reinterpret_cast<uint32_t*>(&h);
}

__device__ __forceinline__ void mma_f16(float* c, uint32_t a0, uint32_t a1,
                                        uint32_t a2, uint32_t a3,
                                        uint32_t b0, uint32_t b1) {
    asm volatile(
        "mma.sync.aligned.m16n8k16.row.col.f32.f16.f16.f32 "
        "{%0,%1,%2,%3}, {%4,%5,%6,%7}, {%8,%9}, {%0,%1,%2,%3};"
        : "+f"(c[0]), "+f"(c[1]), "+f"(c[2]), "+f"(c[3])
        : "r"(a0), "r"(a1), "r"(a2), "r"(a3), "r"(b0), "r"(b1));
}

__device__ __forceinline__ void ldsm4(uint32_t& r0, uint32_t& r1,
                                      uint32_t& r2, uint32_t& r3, uint32_t addr) {
    asm volatile("ldmatrix.sync.aligned.m8n8.x4.shared.b16 {%0,%1,%2,%3}, [%4];"
                 : "=r"(r0), "=r"(r1), "=r"(r2), "=r"(r3) : "r"(addr));
}

__device__ __forceinline__ uint32_t smem_u32(const void* p) {
    uint32_t a;
    asm("{ .reg .u64 t; cvta.to.shared.u64 t, %1; cvt.u32.u64 %0, t; }"
        : "=r"(a) : "l"(p));
    return a;
}

// ===========================================================================
// Prep W1: pack W1^T into per-lane fp16 A-fragment order (m16n8k16).
//   idx = ((q*32 + kstep)*2 + s)*32 + lane,  q in 0..7
// ===========================================================================
__global__ __launch_bounds__(256) void prep_w1(const float* __restrict__ W1) {
    int idx   = blockIdx.x * 256 + threadIdx.x;   // 0..16383
    int lane  = idx & 31;
    int s     = (idx >> 5) & 1;
    int kstep = (idx >> 6) & 31;
    int q     = (idx >> 11) & 7;

    int n0 = q * 32 + s * 16 + (lane >> 2);
    int k0 = kstep * 16 + (lane & 3) * 2;

    uint4 o;
    o.x = h2u(__floats2half2_rn(W1[(long)k0 * N1 + n0],       W1[(long)(k0 + 1) * N1 + n0]));
    o.y = h2u(__floats2half2_rn(W1[(long)k0 * N1 + n0 + 8],   W1[(long)(k0 + 1) * N1 + n0 + 8]));
    o.z = h2u(__floats2half2_rn(W1[(long)(k0 + 8) * N1 + n0],     W1[(long)(k0 + 9) * N1 + n0]));
    o.w = h2u(__floats2half2_rn(W1[(long)(k0 + 8) * N1 + n0 + 8], W1[(long)(k0 + 9) * N1 + n0 + 8]));
    g_w1pack[idx] = o;
}

// ===========================================================================
// Prep W2: pack W2 [K=256][S=63] into per-lane fp16 B-fragment order.
// ===========================================================================
__global__ __launch_bounds__(256) void prep_w2(const float* __restrict__ W2) {
    int idx  = blockIdx.x * 256 + threadIdx.x;   // 0..4095
    int lane = idx & 31;
    int nb   = (idx >> 5) & 7;
    int kt   = idx >> 8;
    int k = kt * 16 + (lane & 3) * 2;
    int n = nb * 8 + (lane >> 2);
    float w00 = (n < S_) ? W2[(long)k * S_ + n]       : 0.f;
    float w01 = (n < S_) ? W2[(long)(k + 1) * S_ + n] : 0.f;
    float w10 = (n < S_) ? W2[(long)(k + 8) * S_ + n] : 0.f;
    float w11 = (n < S_) ? W2[(long)(k + 9) * S_ + n] : 0.f;
    uint2 o;
    o.x = h2u(__floats2half2_rn(w00, w01));
    o.y = h2u(__floats2half2_rn(w10, w11));
    g_w2pack[idx] = o;
}

// ===========================================================================
// GEMM1 (fp16 mma.sync + ldmatrix): h = relu(pairs @ W1 + b1)
//   CTA 256(hid) x 128(m), 512 threads = 16 warps (8 nb x 2 mb), K=512.
//   Epilogue writes h directly in gemm2 A-fragment order (g_hfrag).
// ===========================================================================
#define BSTW 20   // uint32 words per B row (40 halfs = 80 bytes: 64 data + 16 pad)
__global__ __launch_bounds__(512, 1) void gemm1_tc(
    const float* __restrict__ emb, const float* __restrict__ b1)
{
    extern __shared__ __align__(16) char dynsm[];
    uint32_t* sB0 = reinterpret_cast<uint32_t*>(dynsm);   // [2][128*20] mainloop
    __half*   sT  = reinterpret_cast<__half*>(dynsm);     // [128][264] epilogue
    const uint32_t sbAddr = smem_u32(dynsm);

    const int tid  = threadIdx.x;
    const int warp = tid >> 5;
    const int lane = tid & 31;
    const int g    = lane >> 2;
    const int t    = lane & 3;
    const int wq   = warp & 7;     // hidden 32-block (0..7)
    const int wm   = warp >> 3;    // m 64-block (0..1)
    const int mBase = blockIdx.x * 128;

    // ldmatrix addressing: lane supplies row for matrix q=lane/8, row lane%8
    const int lmJ     = (lane >> 4);         // 0/1: which j within the pair
    const int lmPiece = (lane >> 3) & 1;     // 0/1: b0 or b1 (k piece)
    const int lmRow   = lane & 7;

    // B-stage mapping: 4 threads per row, 8 k-values each
    const int r  = tid >> 2;             // 0..127
    const int ch = (tid & 3) * 8;        // 0,8,16,24
    int m = mBase + r;
    if (m >= M1) m = M1 - 1;
    const int b = m / TM1;
    const int tt = m - b * TM1;
    const float* rowT  = emb + ((long)b * T_ + tt) * H_;   // pairs k>=256
    const float* rowT1 = rowT + H_;                        // pairs k<256

    float acc[2][8][4];
    #pragma unroll
    for (int s = 0; s < 2; s++)
        #pragma unroll
        for (int j = 0; j < 8; j++)
            #pragma unroll
            for (int d = 0; d < 4; d++) acc[s][j][d] = 0.f;

    // prologue: stage kt=0
    {
        float4 v0 = *reinterpret_cast<const float4*>(rowT1 + ch);
        float4 v1 = *reinterpret_cast<const float4*>(rowT1 + ch + 4);
        uint4 o;
        o.x = h2u(__floats2half2_rn(v0.x, v0.y));
        o.y = h2u(__floats2half2_rn(v0.z, v0.w));
        o.z = h2u(__floats2half2_rn(v1.x, v1.y));
        o.w = h2u(__floats2half2_rn(v1.z, v1.w));
        *reinterpret_cast<uint4*>(&sB0[r * BSTW + ch / 2]) = o;
    }
    __syncthreads();

    for (int kt = 0; kt < 16; kt++) {
        const int cur = kt & 1;
        const uint32_t sCaddr = sbAddr + cur * (128 * BSTW * 4);

        // prefetch next tile's global loads
        float4 vn0, vn1;
        if (kt < 15) {
            const int kg = (kt + 1) * 32;
            const float* src = (kg < H_) ? (rowT1 + kg) : (rowT + (kg - H_));
            vn0 = *reinterpret_cast<const float4*>(src + ch);
            vn1 = *reinterpret_cast<const float4*>(src + ch + 4);
        }

        #pragma unroll
        for (int ks = 0; ks < 2; ks++) {
            long aIdx = (((long)(wq * 32 + kt * 2 + ks)) * 2) * 32 + lane;
            uint4 A0 = g_w1pack[aIdx];        // s=0: n0, n0+8
            uint4 A1 = g_w1pack[aIdx + 32];   // s=1: n0+16, n0+24

            #pragma unroll
            for (int jp = 0; jp < 4; jp++) {
                int jm = jp * 2 + lmJ;
                uint32_t addr = sCaddr + (wm * 64 + jm * 8 + lmRow) * 80
                              + ks * 32 + lmPiece * 16;
                uint32_t r0, r1, r2, r3;
                ldsm4(r0, r1, r2, r3, addr);   // r0,r1: j=jp*2; r2,r3: j=jp*2+1
                mma_f16(acc[0][jp * 2],     A0.x, A0.y, A0.z, A0.w, r0, r1);
                mma_f16(acc[1][jp * 2],     A1.x, A1.y, A1.z, A1.w, r0, r1);
                mma_f16(acc[0][jp * 2 + 1], A0.x, A0.y, A0.z, A0.w, r2, r3);
                mma_f16(acc[1][jp * 2 + 1], A1.x, A1.y, A1.z, A1.w, r2, r3);
            }
        }

        if (kt < 15) {
            uint32_t* sN = sB0 + (cur ^ 1) * (128 * BSTW);
            uint4 o;
            o.x = h2u(__floats2half2_rn(vn0.x, vn0.y));
            o.y = h2u(__floats2half2_rn(vn0.z, vn0.w));
            o.z = h2u(__floats2half2_rn(vn1.x, vn1.y));
            o.w = h2u(__floats2half2_rn(vn1.z, vn1.w));
            *reinterpret_cast<uint4*>(&sN[r * BSTW + ch / 2]) = o;
        }
        __syncthreads();
    }

    // Epilogue pass 1: +b1, relu, fp16 -> smem [m 128][hid 256 (stride 264)]
    #pragma unroll
    for (int s = 0; s < 2; s++) {
        int n_g = wq * 32 + s * 16 + g;
        float bn0 = __ldg(&b1[n_g]);
        float bn8 = __ldg(&b1[n_g + 8]);
        #pragma unroll
        for (int j = 0; j < 8; j++) {
            int m_loc = wm * 64 + j * 8 + t * 2;
            sT[m_loc * 264 + n_g]           = __float2half(fmaxf(acc[s][j][0] + bn0, 0.f));
            sT[(m_loc + 1) * 264 + n_g]     = __float2half(fmaxf(acc[s][j][1] + bn0, 0.f));
            sT[m_loc * 264 + n_g + 8]       = __float2half(fmaxf(acc[s][j][2] + bn8, 0.f));
            sT[(m_loc + 1) * 264 + n_g + 8] = __float2half(fmaxf(acc[s][j][3] + bn8, 0.f));
        }
    }
    __syncthreads();

    // Epilogue pass 2: frag-pack to g_hfrag.  warp -> kt, mb loop 0..7.
    //   a0 = h[mb*16+g][kt*16+t*2 .. +1], a1 = row+8, a2 = col+8, a3 = both
    {
        const int kt = warp;             // 0..15
        const int col = kt * 16 + t * 2;
        const long mblkBase = (long)(mBase >> 4);
        #pragma unroll
        for (int mb = 0; mb < 8; mb++) {
            int row = mb * 16 + g;
            uint4 o;
            o.x = *reinterpret_cast<const uint32_t*>(&sT[row * 264 + col]);
            o.y = *reinterpret_cast<const uint32_t*>(&sT[(row + 8) * 264 + col]);
            o.z = *reinterpret_cast<const uint32_t*>(&sT[row * 264 + col + 8]);
            o.w = *reinterpret_cast<const uint32_t*>(&sT[(row + 8) * 264 + col + 8]);
            g_hfrag[((mblkBase + mb) * 16 + kt) * 32 + lane] = o;
        }
    }
}

// ===========================================================================
// GEMM2 (fp16 mma.sync, frag-packed A): trans = h @ W2 + b2
//   Warp tile 32(m) x 64(n); CTA 256(m); K=256 in 16 ktiles; grid 250.
//   A: 2 x LDG.128/ktile (g_hfrag), B: 8 x LDG.64/ktile (g_w2pack).
// ===========================================================================
__global__ __launch_bounds__(256, 2) void gemm2_tc(const float* __restrict__ b2) {
    extern __shared__ __align__(16) float sm2[];   // [256][65]

    const int tid  = threadIdx.x;
    const int warp = tid >> 5;
    const int lane = tid & 31;
    const int g = lane >> 2;
    const int t = lane & 3;
    const long mblk0 = (long)blockIdx.x * 16 + warp * 2;

    float acc[2][8][4];
    #pragma unroll
    for (int mf = 0; mf < 2; mf++)
        #pragma unroll
        for (int nb = 0; nb < 8; nb++)
            #pragma unroll
            for (int d = 0; d < 4; d++) acc[mf][nb][d] = 0.f;

    uint4 Af0 = g_hfrag[(mblk0 * 16 + 0) * 32 + lane];
    uint4 Af1 = g_hfrag[((mblk0 + 1) * 16 + 0) * 32 + lane];

    #pragma unroll
    for (int kt = 0; kt < 16; kt++) {
        uint4 An0, An1;
        if (kt < 15) {
            An0 = g_hfrag[(mblk0 * 16 + kt + 1) * 32 + lane];
            An1 = g_hfrag[((mblk0 + 1) * 16 + kt + 1) * 32 + lane];
        }

        #pragma unroll
        for (int nb = 0; nb < 8; nb++) {
            uint2 bf = __ldg(&g_w2pack[((long)kt * 8 + nb) * 32 + lane]);
            mma_f16(acc[0][nb], Af0.x, Af0.y, Af0.z, Af0.w, bf.x, bf.y);
            mma_f16(acc[1][nb], Af1.x, Af1.y, Af1.z, Af1.w, bf.x, bf.y);
        }

        if (kt < 15) { Af0 = An0; Af1 = An1; }
    }

    // stage to smem [m 256][n 64 (pad 65)]
    #pragma unroll
    for (int mf = 0; mf < 2; mf++) {
        int mr = warp * 32 + mf * 16 + g;
        #pragma unroll
        for (int nb = 0; nb < 8; nb++) {
            int n = nb * 8 + t * 2;
            sm2[mr * 65 + n]           = acc[mf][nb][0];
            sm2[mr * 65 + n + 1]       = acc[mf][nb][1];
            sm2[(mr + 8) * 65 + n]     = acc[mf][nb][2];
            sm2[(mr + 8) * 65 + n + 1] = acc[mf][nb][3];
        }
    }
    __syncthreads();

    // coalesced contiguous store: 256 rows x 63 = 16128 floats per CTA
    const long base = (long)blockIdx.x * 256 * S_;
    #pragma unroll
    for (int c = 0; c < 63; c++) {
        int idx = c * 256 + tid;
        int mr = idx / S_;
        int n  = idx - mr * S_;
        g_trans[base + idx] = sm2[mr * 65 + n] + __ldg(&b2[n]);
    }
}

// ===========================================================================
// Align: softmax over collapsed forward-backward scores. One warp per (b,t).
// ===========================================================================
__global__ __launch_bounds__(256) void align_kernel(
    const float* __restrict__ logits, const int* __restrict__ kw,
    float* __restrict__ out)
{
    const int warp = threadIdx.x >> 5;
    const int lane = threadIdx.x & 31;
    const int r = blockIdx.x * 8 + warp;
    const int b = r / T_;
    const int t = r - b * T_;

    const float* Lb  = logits  + (long)b * T_ * S_;
    const float* Trb = g_trans + (long)b * TM1 * S_;

    const int s0 = lane;
    const int s1 = lane + 32;
    const bool has1 = (s1 < S_);

    float v0, v1;
    if (t == 0) {
        float a0 = Lb[s0];
        float a1 = has1 ? Lb[s1] : -INFINITY;
        float mx = fmaxf(a0, a1);
        #pragma unroll
        for (int o = 16; o > 0; o >>= 1) mx = fmaxf(mx, __shfl_xor_sync(0xffffffff, mx, o));
        float se = __expf(a0 - mx) + (has1 ? __expf(a1 - mx) : 0.f);
        #pragma unroll
        for (int o = 16; o > 0; o >>= 1) se += __shfl_xor_sync(0xffffffff, se, o);
        float lse = mx + __logf(se);
        int k0 = __ldg(&kw[b * 32]);
        float logp0 = Lb[k0] - lse;
        v0 = ((s0 == 0) ? logp0 : 0.f) + Lb[S_ + s0] + Trb[s0];
        v1 = has1 ? (Lb[S_ + s1] + Trb[s1]) : -INFINITY;
    } else if (t == T_ - 1) {
        v0 = Lb[(long)t * S_ + s0] + Trb[(long)(t - 1) * S_ + s0];
        v1 = has1 ? (Lb[(long)t * S_ + s1] + Trb[(long)(t - 1) * S_ + s1]) : -INFINITY;
    } else {
        v0 = Lb[(long)t * S_ + s0] + Lb[(long)(t + 1) * S_ + s0]
           + Trb[(long)(t - 1) * S_ + s0] + Trb[(long)t * S_ + s0];
        v1 = has1 ? (Lb[(long)t * S_ + s1] + Lb[(long)(t + 1) * S_ + s1]
                   + Trb[(long)(t - 1) * S_ + s1] + Trb[(long)t * S_ + s1])
                  : -INFINITY;
    }

    float mx = fmaxf(v0, v1);
    #pragma unroll
    for (int o = 16; o > 0; o >>= 1) mx = fmaxf(mx, __shfl_xor_sync(0xffffffff, mx, o));
    float e0 = expf(v0 - mx);
    float e1 = has1 ? expf(v1 - mx) : 0.f;
    float sum = e0 + e1;
    #pragma unroll
    for (int o = 16; o > 0; o >>= 1) sum += __shfl_xor_sync(0xffffffff, sum, o);
    float inv = 1.f / sum;

    float* ob = out + (long)r * S_;
    ob[s0] = e0 * inv;
    if (has1) ob[s1] = e1 * inv;
}

// ===========================================================================
extern "C" void kernel_launch(void* const* d_in, const int* in_sizes, int n_in,
                              void* d_out, int out_size) {
    const float* logits = (const float*)d_in[0];   // (B,T,S)
    const float* emb    = (const float*)d_in[1];   // (B,T,H)
    const int*   kw     = (const int*)  d_in[2];   // (B,32)
    const float* W1     = (const float*)d_in[3];   // (2H,H)
    const float* b1     = (const float*)d_in[4];   // (H,)
    const float* W2     = (const float*)d_in[5];   // (H,S)
    const float* b2     = (const float*)d_in[6];   // (S,)
    float*       out    = (float*)d_out;           // (B,T,S)

    const int smem1 = 128 * 264 * 2;       // 67584
    const int smem2 = 256 * 65 * 4;        // 66560
    cudaFuncSetAttribute(gemm1_tc, cudaFuncAttributeMaxDynamicSharedMemorySize, smem1);
    cudaFuncSetAttribute(gemm2_tc, cudaFuncAttributeMaxDynamicSharedMemorySize, smem2);

    prep_w1<<<64, 256>>>(W1);
    prep_w2<<<16, 256>>>(W2);
    gemm1_tc<<<500, 512, smem1>>>(emb, b1);
    gemm2_tc<<<250, 256, smem2>>>(b2);
    align_kernel<<<(B_ * T_) / 8, 256>>>(logits, kw, out);
}

// round 8
// speedup vs baseline: 4.7253x; 1.1617x over previous
#include <cuda_runtime.h>
#include <cuda_fp16.h>
#include <math.h>
#include <cstdint>

#define B_   32
#define T_   2000
#define H_   256
#define S_   63
#define TM1  1999            // T-1
#define M1   63968           // B*(T-1)
#define M1P  64000           // padded row count
#define K1   512             // 2*H
#define N1   256             // H

// Scratch (device globals: allocation-guard safe)
__device__ __align__(16) uint4    g_hfrag[4000 * 16 * 32]; // h fp16, gemm2 A-frag packed
__device__ __align__(16) float    g_trans[M1P * S_];       // transition scores
__device__ __align__(16) uint4    g_w1pack[16384];         // W1^T fp16 A-frags
__device__ __align__(16) uint2    g_w2pack[4096];          // W2 fp16 B-frags

__device__ __forceinline__ uint32_t h2u(__half2 h) {
    return *reinterpret_cast<uint32_t*>(&h);
}

__device__ __forceinline__ void mma_f16(float* c, uint32_t a0, uint32_t a1,
                                        uint32_t a2, uint32_t a3,
                                        uint32_t b0, uint32_t b1) {
    asm volatile(
        "mma.sync.aligned.m16n8k16.row.col.f32.f16.f16.f32 "
        "{%0,%1,%2,%3}, {%4,%5,%6,%7}, {%8,%9}, {%0,%1,%2,%3};"
        : "+f"(c[0]), "+f"(c[1]), "+f"(c[2]), "+f"(c[3])
        : "r"(a0), "r"(a1), "r"(a2), "r"(a3), "r"(b0), "r"(b1));
}

__device__ __forceinline__ void ldsm4(uint32_t& r0, uint32_t& r1,
                                      uint32_t& r2, uint32_t& r3, uint32_t addr) {
    asm volatile("ldmatrix.sync.aligned.m8n8.x4.shared.b16 {%0,%1,%2,%3}, [%4];"
                 : "=r"(r0), "=r"(r1), "=r"(r2), "=r"(r3) : "r"(addr));
}

__device__ __forceinline__ uint32_t smem_u32(const void* p) {
    uint32_t a;
    asm("{ .reg .u64 t; cvta.to.shared.u64 t, %1; cvt.u32.u64 %0, t; }"
        : "=r"(a) : "l"(p));
    return a;
}

// ===========================================================================
// Prep W1: pack W1^T into per-lane fp16 A-fragment order (m16n8k16).
// ===========================================================================
__global__ __launch_bounds__(256) void prep_w1(const float* __restrict__ W1) {
    int idx   = blockIdx.x * 256 + threadIdx.x;   // 0..16383
    int lane  = idx & 31;
    int s     = (idx >> 5) & 1;
    int kstep = (idx >> 6) & 31;
    int q     = (idx >> 11) & 7;

    int n0 = q * 32 + s * 16 + (lane >> 2);
    int k0 = kstep * 16 + (lane & 3) * 2;

    uint4 o;
    o.x = h2u(__floats2half2_rn(W1[(long)k0 * N1 + n0],       W1[(long)(k0 + 1) * N1 + n0]));
    o.y = h2u(__floats2half2_rn(W1[(long)k0 * N1 + n0 + 8],   W1[(long)(k0 + 1) * N1 + n0 + 8]));
    o.z = h2u(__floats2half2_rn(W1[(long)(k0 + 8) * N1 + n0],     W1[(long)(k0 + 9) * N1 + n0]));
    o.w = h2u(__floats2half2_rn(W1[(long)(k0 + 8) * N1 + n0 + 8], W1[(long)(k0 + 9) * N1 + n0 + 8]));
    g_w1pack[idx] = o;
}

// ===========================================================================
// Prep W2: pack W2 [K=256][S=63] into per-lane fp16 B-fragment order.
// ===========================================================================
__global__ __launch_bounds__(256) void prep_w2(const float* __restrict__ W2) {
    int idx  = blockIdx.x * 256 + threadIdx.x;   // 0..4095
    int lane = idx & 31;
    int nb   = (idx >> 5) & 7;
    int kt   = idx >> 8;
    int k = kt * 16 + (lane & 3) * 2;
    int n = nb * 8 + (lane >> 2);
    float w00 = (n < S_) ? W2[(long)k * S_ + n]       : 0.f;
    float w01 = (n < S_) ? W2[(long)(k + 1) * S_ + n] : 0.f;
    float w10 = (n < S_) ? W2[(long)(k + 8) * S_ + n] : 0.f;
    float w11 = (n < S_) ? W2[(long)(k + 9) * S_ + n] : 0.f;
    uint2 o;
    o.x = h2u(__floats2half2_rn(w00, w01));
    o.y = h2u(__floats2half2_rn(w10, w11));
    g_w2pack[idx] = o;
}

// ===========================================================================
// GEMM1 (fp16 mma.sync + ldmatrix): h = relu(pairs @ W1 + b1)
//   CTA 256(hid) x 64(m), 256 threads = 8 warps (one n 32-block each), K=512.
//   grid=1000, 2 CTAs/SM -> finer wave quantization + cross-CTA overlap.
// ===========================================================================
#define BSTW 20   // uint32 words per B row (40 halfs = 80 bytes)
__global__ __launch_bounds__(256, 2) void gemm1_tc(
    const float* __restrict__ emb, const float* __restrict__ b1)
{
    extern __shared__ __align__(16) char dynsm[];
    uint32_t* sB0 = reinterpret_cast<uint32_t*>(dynsm);   // [2][64*20] mainloop
    __half*   sT  = reinterpret_cast<__half*>(dynsm);     // [64][264] epilogue
    const uint32_t sbAddr = smem_u32(dynsm);

    const int tid  = threadIdx.x;
    const int warp = tid >> 5;     // = wq, hidden 32-block (0..7)
    const int lane = tid & 31;
    const int g    = lane >> 2;
    const int t    = lane & 3;
    const int mBase = blockIdx.x * 64;

    // ldmatrix addressing
    const int lmJ     = (lane >> 4);
    const int lmPiece = (lane >> 3) & 1;
    const int lmRow   = lane & 7;

    // B-stage mapping: 4 threads per row, 8 k-values each
    const int r  = tid >> 2;             // 0..63
    const int ch = (tid & 3) * 8;        // 0,8,16,24
    int m = mBase + r;
    if (m >= M1) m = M1 - 1;
    const int b = m / TM1;
    const int tt = m - b * TM1;
    const float* rowT  = emb + ((long)b * T_ + tt) * H_;   // pairs k>=256
    const float* rowT1 = rowT + H_;                        // pairs k<256

    float acc[2][8][4];
    #pragma unroll
    for (int s = 0; s < 2; s++)
        #pragma unroll
        for (int j = 0; j < 8; j++)
            #pragma unroll
            for (int d = 0; d < 4; d++) acc[s][j][d] = 0.f;

    // prologue: stage kt=0
    {
        float4 v0 = *reinterpret_cast<const float4*>(rowT1 + ch);
        float4 v1 = *reinterpret_cast<const float4*>(rowT1 + ch + 4);
        uint4 o;
        o.x = h2u(__floats2half2_rn(v0.x, v0.y));
        o.y = h2u(__floats2half2_rn(v0.z, v0.w));
        o.z = h2u(__floats2half2_rn(v1.x, v1.y));
        o.w = h2u(__floats2half2_rn(v1.z, v1.w));
        *reinterpret_cast<uint4*>(&sB0[r * BSTW + ch / 2]) = o;
    }
    __syncthreads();

    for (int kt = 0; kt < 16; kt++) {
        const int cur = kt & 1;
        const uint32_t sCaddr = sbAddr + cur * (64 * BSTW * 4);

        // prefetch next tile's global loads
        float4 vn0, vn1;
        if (kt < 15) {
            const int kg = (kt + 1) * 32;
            const float* src = (kg < H_) ? (rowT1 + kg) : (rowT + (kg - H_));
            vn0 = *reinterpret_cast<const float4*>(src + ch);
            vn1 = *reinterpret_cast<const float4*>(src + ch + 4);
        }

        #pragma unroll
        for (int ks = 0; ks < 2; ks++) {
            long aIdx = (((long)(warp * 32 + kt * 2 + ks)) * 2) * 32 + lane;
            uint4 A0 = g_w1pack[aIdx];        // s=0: n0, n0+8
            uint4 A1 = g_w1pack[aIdx + 32];   // s=1: n0+16, n0+24

            #pragma unroll
            for (int jp = 0; jp < 4; jp++) {
                int jm = jp * 2 + lmJ;
                uint32_t addr = sCaddr + (jm * 8 + lmRow) * 80
                              + ks * 32 + lmPiece * 16;
                uint32_t r0, r1, r2, r3;
                ldsm4(r0, r1, r2, r3, addr);
                mma_f16(acc[0][jp * 2],     A0.x, A0.y, A0.z, A0.w, r0, r1);
                mma_f16(acc[1][jp * 2],     A1.x, A1.y, A1.z, A1.w, r0, r1);
                mma_f16(acc[0][jp * 2 + 1], A0.x, A0.y, A0.z, A0.w, r2, r3);
                mma_f16(acc[1][jp * 2 + 1], A1.x, A1.y, A1.z, A1.w, r2, r3);
            }
        }

        if (kt < 15) {
            uint32_t* sN = sB0 + (cur ^ 1) * (64 * BSTW);
            uint4 o;
            o.x = h2u(__floats2half2_rn(vn0.x, vn0.y));
            o.y = h2u(__floats2half2_rn(vn0.z, vn0.w));
            o.z = h2u(__floats2half2_rn(vn1.x, vn1.y));
            o.w = h2u(__floats2half2_rn(vn1.z, vn1.w));
            *reinterpret_cast<uint4*>(&sN[r * BSTW + ch / 2]) = o;
        }
        __syncthreads();
    }

    // Epilogue pass 1: +b1, relu, fp16 -> smem [m 64][hid 256 (stride 264)]
    #pragma unroll
    for (int s = 0; s < 2; s++) {
        int n_g = warp * 32 + s * 16 + g;
        float bn0 = __ldg(&b1[n_g]);
        float bn8 = __ldg(&b1[n_g + 8]);
        #pragma unroll
        for (int j = 0; j < 8; j++) {
            int m_loc = j * 8 + t * 2;
            sT[m_loc * 264 + n_g]           = __float2half(fmaxf(acc[s][j][0] + bn0, 0.f));
            sT[(m_loc + 1) * 264 + n_g]     = __float2half(fmaxf(acc[s][j][1] + bn0, 0.f));
            sT[m_loc * 264 + n_g + 8]       = __float2half(fmaxf(acc[s][j][2] + bn8, 0.f));
            sT[(m_loc + 1) * 264 + n_g + 8] = __float2half(fmaxf(acc[s][j][3] + bn8, 0.f));
        }
    }
    __syncthreads();

    // Epilogue pass 2: frag-pack to g_hfrag.  warp -> 2 kts, 4 m16-blocks.
    {
        const long mblkBase = (long)blockIdx.x * 4;
        #pragma unroll
        for (int ktl = 0; ktl < 2; ktl++) {
            const int kt = warp * 2 + ktl;
            const int col = kt * 16 + t * 2;
            #pragma unroll
            for (int mb = 0; mb < 4; mb++) {
                int row = mb * 16 + g;
                uint4 o;
                o.x = *reinterpret_cast<const uint32_t*>(&sT[row * 264 + col]);
                o.y = *reinterpret_cast<const uint32_t*>(&sT[(row + 8) * 264 + col]);
                o.z = *reinterpret_cast<const uint32_t*>(&sT[row * 264 + col + 8]);
                o.w = *reinterpret_cast<const uint32_t*>(&sT[(row + 8) * 264 + col + 8]);
                g_hfrag[((mblkBase + mb) * 16 + kt) * 32 + lane] = o;
            }
        }
    }
}

// ===========================================================================
// GEMM2 (fp16 mma.sync, frag-packed A): trans = h @ W2 + b2
//   Warp tile 32(m) x 64(n); CTA 256(m); K=256 in 16 ktiles; grid 250.
// ===========================================================================
__global__ __launch_bounds__(256, 2) void gemm2_tc(const float* __restrict__ b2) {
    extern __shared__ __align__(16) float sm2[];   // [256][65]

    const int tid  = threadIdx.x;
    const int warp = tid >> 5;
    const int lane = tid & 31;
    const int g = lane >> 2;
    const int t = lane & 3;
    const long mblk0 = (long)blockIdx.x * 16 + warp * 2;

    float acc[2][8][4];
    #pragma unroll
    for (int mf = 0; mf < 2; mf++)
        #pragma unroll
        for (int nb = 0; nb < 8; nb++)
            #pragma unroll
            for (int d = 0; d < 4; d++) acc[mf][nb][d] = 0.f;

    uint4 Af0 = g_hfrag[(mblk0 * 16 + 0) * 32 + lane];
    uint4 Af1 = g_hfrag[((mblk0 + 1) * 16 + 0) * 32 + lane];

    #pragma unroll
    for (int kt = 0; kt < 16; kt++) {
        uint4 An0, An1;
        if (kt < 15) {
            An0 = g_hfrag[(mblk0 * 16 + kt + 1) * 32 + lane];
            An1 = g_hfrag[((mblk0 + 1) * 16 + kt + 1) * 32 + lane];
        }

        #pragma unroll
        for (int nb = 0; nb < 8; nb++) {
            uint2 bf = __ldg(&g_w2pack[((long)kt * 8 + nb) * 32 + lane]);
            mma_f16(acc[0][nb], Af0.x, Af0.y, Af0.z, Af0.w, bf.x, bf.y);
            mma_f16(acc[1][nb], Af1.x, Af1.y, Af1.z, Af1.w, bf.x, bf.y);
        }

        if (kt < 15) { Af0 = An0; Af1 = An1; }
    }

    // stage to smem [m 256][n 64 (pad 65)]
    #pragma unroll
    for (int mf = 0; mf < 2; mf++) {
        int mr = warp * 32 + mf * 16 + g;
        #pragma unroll
        for (int nb = 0; nb < 8; nb++) {
            int n = nb * 8 + t * 2;
            sm2[mr * 65 + n]           = acc[mf][nb][0];
            sm2[mr * 65 + n + 1]       = acc[mf][nb][1];
            sm2[(mr + 8) * 65 + n]     = acc[mf][nb][2];
            sm2[(mr + 8) * 65 + n + 1] = acc[mf][nb][3];
        }
    }
    __syncthreads();

    // coalesced contiguous store: 256 rows x 63 = 16128 floats per CTA
    const long base = (long)blockIdx.x * 256 * S_;
    #pragma unroll
    for (int c = 0; c < 63; c++) {
        int idx = c * 256 + tid;
        int mr = idx / S_;
        int n  = idx - mr * S_;
        g_trans[base + idx] = sm2[mr * 65 + n] + __ldg(&b2[n]);
    }
}

// ===========================================================================
// Align: softmax over collapsed forward-backward scores.
//   One warp per 8 consecutive t of one b; carries lp/tr rows in registers
//   (each logits/trans row loaded ~once instead of twice).
// ===========================================================================
#define TW 8
__global__ __launch_bounds__(256) void align_kernel(
    const float* __restrict__ logits, const int* __restrict__ kw,
    float* __restrict__ out)
{
    const int warp = threadIdx.x >> 5;
    const int lane = threadIdx.x & 31;
    const int task = blockIdx.x * 8 + warp;       // 0..7999
    const int b = task / (T_ / TW);
    const int t0 = (task - b * (T_ / TW)) * TW;

    const float* Lb  = logits  + (long)b * T_ * S_;
    const float* Trb = g_trans + (long)b * TM1 * S_;

    const int s0 = lane;
    const int s1 = lane + 32;
    const bool has1 = (s1 < S_);

    // carries: lp[t] and tr[t-1]
    float lpc0 = __ldg(&Lb[(long)t0 * S_ + s0]);
    float lpc1 = has1 ? __ldg(&Lb[(long)t0 * S_ + s1]) : 0.f;
    float trp0 = 0.f, trp1 = 0.f;
    if (t0 > 0) {
        trp0 = __ldg(&Trb[(long)(t0 - 1) * S_ + s0]);
        if (has1) trp1 = __ldg(&Trb[(long)(t0 - 1) * S_ + s1]);
    }

    #pragma unroll
    for (int i = 0; i < TW; i++) {
        const int t = t0 + i;
        float lpn0 = 0.f, lpn1 = 0.f, trc0 = 0.f, trc1 = 0.f;
        if (t < T_ - 1) {
            lpn0 = __ldg(&Lb[(long)(t + 1) * S_ + s0]);
            trc0 = __ldg(&Trb[(long)t * S_ + s0]);
            if (has1) {
                lpn1 = __ldg(&Lb[(long)(t + 1) * S_ + s1]);
                trc1 = __ldg(&Trb[(long)t * S_ + s1]);
            }
        }

        float v0, v1;
        if (t == 0) {
            float a0 = lpc0;
            float a1 = has1 ? lpc1 : -INFINITY;
            float mx = fmaxf(a0, a1);
            #pragma unroll
            for (int o = 16; o > 0; o >>= 1) mx = fmaxf(mx, __shfl_xor_sync(0xffffffff, mx, o));
            float se = __expf(a0 - mx) + (has1 ? __expf(a1 - mx) : 0.f);
            #pragma unroll
            for (int o = 16; o > 0; o >>= 1) se += __shfl_xor_sync(0xffffffff, se, o);
            float lse = mx + __logf(se);
            int k0 = __ldg(&kw[b * 32]);
            float logp0 = __ldg(&Lb[k0]) - lse;
            v0 = ((s0 == 0) ? logp0 : 0.f) + lpn0 + trc0;
            v1 = has1 ? (lpn1 + trc1) : -INFINITY;
        } else if (t == T_ - 1) {
            v0 = lpc0 + trp0;
            v1 = has1 ? (lpc1 + trp1) : -INFINITY;
        } else {
            v0 = lpc0 + lpn0 + trp0 + trc0;
            v1 = has1 ? (lpc1 + lpn1 + trp1 + trc1) : -INFINITY;
        }

        float mx = fmaxf(v0, v1);
        #pragma unroll
        for (int o = 16; o > 0; o >>= 1) mx = fmaxf(mx, __shfl_xor_sync(0xffffffff, mx, o));
        float e0 = __expf(v0 - mx);
        float e1 = has1 ? __expf(v1 - mx) : 0.f;
        float sum = e0 + e1;
        #pragma unroll
        for (int o = 16; o > 0; o >>= 1) sum += __shfl_xor_sync(0xffffffff, sum, o);
        float inv = 1.f / sum;

        float* ob = out + ((long)b * T_ + t) * S_;
        ob[s0] = e0 * inv;
        if (has1) ob[s1] = e1 * inv;

        lpc0 = lpn0; lpc1 = lpn1;
        trp0 = trc0; trp1 = trc1;
    }
}

// ===========================================================================
extern "C" void kernel_launch(void* const* d_in, const int* in_sizes, int n_in,
                              void* d_out, int out_size) {
    const float* logits = (const float*)d_in[0];   // (B,T,S)
    const float* emb    = (const float*)d_in[1];   // (B,T,H)
    const int*   kw     = (const int*)  d_in[2];   // (B,32)
    const float* W1     = (const float*)d_in[3];   // (2H,H)
    const float* b1     = (const float*)d_in[4];   // (H,)
    const float* W2     = (const float*)d_in[5];   // (H,S)
    const float* b2     = (const float*)d_in[6];   // (S,)
    float*       out    = (float*)d_out;           // (B,T,S)

    const int smem1 = 64 * 264 * 2;        // 33792 (>= 2*64*20*4 = 10240)
    const int smem2 = 256 * 65 * 4;        // 66560
    cudaFuncSetAttribute(gemm1_tc, cudaFuncAttributeMaxDynamicSharedMemorySize, smem1);
    cudaFuncSetAttribute(gemm2_tc, cudaFuncAttributeMaxDynamicSharedMemorySize, smem2);

    prep_w1<<<64, 256>>>(W1);
    prep_w2<<<16, 256>>>(W2);
    gemm1_tc<<<1000, 256, smem1>>>(emb, b1);
    gemm2_tc<<<250, 256, smem2>>>(b2);
    align_kernel<<<(B_ * (T_ / TW)) / 8, 256>>>(logits, kw, out);
}